// round 1
// baseline (speedup 1.0000x reference)
#include <cuda_runtime.h>

// Problem constants
#define BATCH 2
#define CH    256
#define HH    64
#define WWID  64
#define NPIX  4096            // HH*WWID
#define MIPC  8
#define CQD   32
#define CN    (CH*NPIX)       // 1048576 per batch per C-channel tensor

// ---------------- static scratch (allocation-free rule) ----------------
__device__ float g_pool[BATCH*CH*128];
__device__ float g_yca [BATCH*MIPC*128];
__device__ float g_ah  [BATCH*CH*HH];
__device__ float g_aw  [BATCH*CH*WWID];
__device__ float g_r   [BATCH*CN];
__device__ float g_t1  [BATCH*CN];
__device__ float g_cat [BATCH*4*CN];
__device__ float g_col [(long)BATCH*9*CN];       // im2col: [b][2304][4096]
__device__ float g_yc  [BATCH*2*CN];
__device__ float g_res [BATCH*CN];
__device__ float g_q   [BATCH*CQD*NPIX];
__device__ float g_kb  [BATCH*CQD*NPIX];
__device__ float g_qt  [BATCH*NPIX*CQD];
__device__ float g_v   [BATCH*CN];
__device__ float g_attn[(long)BATCH*NPIX*NPIX];  // 134 MB
__device__ float g_pam [BATCH*CN];
__device__ float g_e   [BATCH*CH*CH];
__device__ float g_ac  [BATCH*CH*CH];
__device__ float g_cam [BATCH*CN];
// folded conv+BN weights
__device__ float g_w1f[MIPC*CH];   __device__ float g_b1f[MIPC];
__device__ float g_ws1[CH*CH];     __device__ float g_bs1[CH];
__device__ float g_ws2[CH*CH];     __device__ float g_bs2[CH];
__device__ float g_ws3[CH*CH*9];   __device__ float g_bs3[CH];
__device__ float g_ws4[CH*CH];     __device__ float g_bs4[CH];
__device__ float g_ws5[CH*4*CH];   __device__ float g_bs5[CH];
__device__ float g_ws6[CH*CH*9];   __device__ float g_bs6[CH];
__device__ float g_ws7[CH*2*CH];   __device__ float g_bs7[CH];

// ---------------- BN folding: W' = W*s, b' = b_in*s + beta - mean*s ----
__global__ void fold_bn_k(const float* __restrict__ w, const float* __restrict__ bn,
                          const float* __restrict__ bin,
                          float* __restrict__ wf, float* __restrict__ bf,
                          int O, int Ke)
{
    int o = blockIdx.x;
    float g  = bn[o];
    float be = bn[O + o];
    float mn = bn[2*O + o];
    float vr = bn[3*O + o];
    float s = g * rsqrtf(vr + 1e-5f);
    for (int k = threadIdx.x; k < Ke; k += blockDim.x)
        wf[(long)o*Ke + k] = w[(long)o*Ke + k] * s;
    if (threadIdx.x == 0)
        bf[o] = (bin ? bin[o] : 0.f) * s + be - mn * s;
}

// ---------------- generic tiled SGEMM with fused bias+activation ------
// C[b][m][n] = act( sum_k A[b][m][k] * Beff[b][k][n] + bias[m] )
// A row-major [M][K] (lda=K). If !TB: Beff[k][n] = B[k*ldb + n].
// If TB: Beff[k][n] = B[n*ldb + k].  C row stride = N.
// ACT: 0 none, 1 SiLU, 2 h-swish, 3 sigmoid
template<int ACT, bool TB>
__global__ __launch_bounds__(256) void gemm_k(
    const float* __restrict__ A, const float* __restrict__ B,
    const float* __restrict__ bias, float* __restrict__ C,
    int M, int N, int K, int ldb,
    long sA, long sB, long sC)
{
    int b = blockIdx.z;
    A += (long)b * sA; B += (long)b * sB; C += (long)b * sC;
    int m0 = blockIdx.y * 64, n0 = blockIdx.x * 64;
    __shared__ float As[16][64];
    __shared__ float Bs[16][65];
    int tid = threadIdx.x;
    int tx = tid & 15, ty = tid >> 4;
    float acc[4][4] = {};
    for (int k0 = 0; k0 < K; k0 += 16) {
        { // A tile 64x16
            int i  = tid >> 2;
            int jb = (tid & 3) * 4;
            int m  = m0 + i;
            #pragma unroll
            for (int j = 0; j < 4; j++) {
                int k = k0 + jb + j;
                As[jb + j][i] = (m < M && k < K) ? A[(long)m * K + k] : 0.f;
            }
        }
        if (!TB) { // B tile 16x64, row-major source
            int j  = tid >> 4;        // 0..15
            int nb = (tid & 15) * 4;
            int k  = k0 + j;
            #pragma unroll
            for (int n = 0; n < 4; n++) {
                int nn = n0 + nb + n;
                Bs[j][nb + n] = (k < K && nn < N) ? B[(long)k * ldb + nn] : 0.f;
            }
        } else {   // transposed source: B[n][k]
            int i  = tid >> 2;        // n local
            int jb = (tid & 3) * 4;
            int nn = n0 + i;
            #pragma unroll
            for (int j = 0; j < 4; j++) {
                int k = k0 + jb + j;
                Bs[jb + j][i] = (nn < N && k < K) ? B[(long)nn * ldb + k] : 0.f;
            }
        }
        __syncthreads();
        #pragma unroll
        for (int j = 0; j < 16; j++) {
            float a[4], bb[4];
            #pragma unroll
            for (int i = 0; i < 4; i++) a[i]  = As[j][ty * 4 + i];
            #pragma unroll
            for (int i = 0; i < 4; i++) bb[i] = Bs[j][tx * 4 + i];
            #pragma unroll
            for (int i = 0; i < 4; i++)
                #pragma unroll
                for (int jj = 0; jj < 4; jj++)
                    acc[i][jj] += a[i] * bb[jj];
        }
        __syncthreads();
    }
    #pragma unroll
    for (int i = 0; i < 4; i++) {
        int m = m0 + ty * 4 + i;
        if (m >= M) continue;
        float bv = bias ? bias[m] : 0.f;
        #pragma unroll
        for (int jj = 0; jj < 4; jj++) {
            int n = n0 + tx * 4 + jj;
            if (n >= N) continue;
            float v = acc[i][jj] + bv;
            if (ACT == 1)      v = v / (1.f + __expf(-v));                 // SiLU
            else if (ACT == 2){ float t = fminf(fmaxf(v + 3.f, 0.f), 6.f);
                                v = v * t * (1.f/6.f); }                   // h-swish
            else if (ACT == 3) v = 1.f / (1.f + __expf(-v));               // sigmoid
            C[(long)m * N + n] = v;
        }
    }
}

// ---------------- CoordAtt pooling: mean over W and over H ------------
__global__ void ca_pool_k(const float* __restrict__ x, float* __restrict__ pool)
{
    int c = blockIdx.x, b = blockIdx.y, t = threadIdx.x; // t < 64
    const float* p = x + ((long)b*CH + c) * NPIX;
    float sh = 0.f, sw = 0.f;
    for (int i = 0; i < WWID; i++) sh += p[t*WWID + i];
    for (int i = 0; i < HH;   i++) sw += p[i*WWID + t];
    float* o = pool + ((long)b*CH + c) * 128;
    o[t]      = sh * (1.f/64.f);
    o[64 + t] = sw * (1.f/64.f);
}

__global__ void ca_apply_k(const float* __restrict__ x, float* __restrict__ r)
{
    long i = blockIdx.x * 256L + threadIdx.x;
    if (i >= (long)BATCH*CN) return;
    long bc = i >> 12;             // b*CH + c
    int pix = (int)(i & 4095);
    int y = pix >> 6, xx = pix & 63;
    r[i] = x[i] * g_aw[bc*64 + xx] * g_ah[bc*64 + y];
}

// ---------------- maxpool k=5, stride 1, pad 2 ------------------------
__global__ void maxpool5_k(const float* __restrict__ in, float* __restrict__ out,
                           long bstride)
{
    long i = blockIdx.x * 256L + threadIdx.x;
    if (i >= (long)BATCH*CN) return;
    int b = (int)(i / CN);
    long rem = i - (long)b*CN;
    int c = (int)(rem >> 12);
    int pix = (int)(rem & 4095);
    int y = pix >> 6, x = pix & 63;
    const float* p = in + b*bstride + (long)c*NPIX;
    int y0 = max(y-2,0), y1 = min(y+2,63), x0 = max(x-2,0), x1 = min(x+2,63);
    float m = -3.4e38f;
    for (int yy = y0; yy <= y1; yy++)
        for (int xx = x0; xx <= x1; xx++)
            m = fmaxf(m, p[yy*64 + xx]);
    out[b*bstride + (long)c*NPIX + pix] = m;
}

// ---------------- im2col for 3x3 SAME conv ----------------------------
__global__ void im2col_k(const float* __restrict__ in, float* __restrict__ col)
{
    long i = blockIdx.x * 256L + threadIdx.x;
    const long total = (long)BATCH * 2304 * NPIX;
    if (i >= total) return;
    int n = (int)(i & 4095);
    long r = i >> 12;
    int k = (int)(r % 2304);
    int b = (int)(r / 2304);
    int ci = k / 9, t = k % 9;
    int y = (n >> 6) + t/3 - 1;
    int x = (n & 63) + t%3 - 1;
    float v = 0.f;
    if (y >= 0 && y < 64 && x >= 0 && x < 64)
        v = in[(long)b*CN + (long)ci*NPIX + y*64 + x];
    col[i] = v;
}

// ---------------- transpose q: [b][32][4096] -> [b][4096][32] ---------
__global__ void transpose_q_k(const float* __restrict__ q, float* __restrict__ qt)
{
    long i = blockIdx.x*256L + threadIdx.x;
    if (i >= (long)BATCH*CQD*NPIX) return;
    int n = (int)(i & 4095);
    long r = i >> 12;
    int c = (int)(r % CQD);
    int b = (int)(r / CQD);
    qt[((long)b*NPIX + n)*CQD + c] = q[i];
}

// ---------------- row softmax (PAM, rows of length L) ------------------
__global__ void softmax_row_k(float* __restrict__ a, int L)
{
    float* p = a + (long)blockIdx.x * L;
    __shared__ float sm[256];
    int t = threadIdx.x;
    float m = -3.4e38f;
    for (int i = t; i < L; i += 256) m = fmaxf(m, p[i]);
    sm[t] = m; __syncthreads();
    for (int s = 128; s > 0; s >>= 1) { if (t < s) sm[t] = fmaxf(sm[t], sm[t+s]); __syncthreads(); }
    m = sm[0]; __syncthreads();
    float s = 0.f;
    for (int i = t; i < L; i += 256) s += __expf(p[i] - m);
    sm[t] = s; __syncthreads();
    for (int ss = 128; ss > 0; ss >>= 1) { if (t < ss) sm[t] += sm[t+ss]; __syncthreads(); }
    float inv = 1.f / sm[0];
    for (int i = t; i < L; i += 256) p[i] = __expf(p[i] - m) * inv;
}

// ---------------- CAM softmax: softmax(rowmax - e) over rows of 256 ----
__global__ void cam_softmax_k(const float* __restrict__ e, float* __restrict__ ac)
{
    long row = blockIdx.x;                 // b*256 + c
    const float* p = e + row * 256;
    int t = threadIdx.x;
    __shared__ float sm[256];
    float v = p[t];
    sm[t] = v; __syncthreads();
    for (int s=128; s>0; s>>=1){ if (t<s) sm[t]=fmaxf(sm[t],sm[t+s]); __syncthreads(); }
    float rowmax = sm[0]; __syncthreads();
    float z = rowmax - v;
    sm[t] = z; __syncthreads();
    for (int s=128; s>0; s>>=1){ if (t<s) sm[t]=fmaxf(sm[t],sm[t+s]); __syncthreads(); }
    float zm = sm[0]; __syncthreads();
    float pe = __expf(z - zm);
    sm[t] = pe; __syncthreads();
    for (int s=128; s>0; s>>=1){ if (t<s) sm[t]+=sm[t+s]; __syncthreads(); }
    ac[row*256 + t] = pe / sm[0];
}

// ---------------- final combine ---------------------------------------
__global__ void final_k(const float* __restrict__ gpa, const float* __restrict__ gca,
                        float* __restrict__ out)
{
    long i = blockIdx.x*256L + threadIdx.x;
    if (i >= (long)BATCH*CN) return;
    out[i] = 3.f*g_res[i] + gpa[0]*g_pam[i] + gca[0]*g_cam[i];
}

// ======================================================================
extern "C" void kernel_launch(void* const* d_in, const int* in_sizes, int n_in,
                              void* d_out, int out_size)
{
    const float* x     = (const float*)d_in[0];
    const float* ca_w1 = (const float*)d_in[1];
    const float* ca_b1 = (const float*)d_in[2];
    const float* ca_bn = (const float*)d_in[3];
    const float* ca_wh = (const float*)d_in[4];
    const float* ca_bh = (const float*)d_in[5];
    const float* ca_ww = (const float*)d_in[6];
    const float* ca_bw = (const float*)d_in[7];
    const float* s1_w  = (const float*)d_in[8];  const float* s1_bn = (const float*)d_in[9];
    const float* s2_w  = (const float*)d_in[10]; const float* s2_bn = (const float*)d_in[11];
    const float* s3_w  = (const float*)d_in[12]; const float* s3_bn = (const float*)d_in[13];
    const float* s4_w  = (const float*)d_in[14]; const float* s4_bn = (const float*)d_in[15];
    const float* s5_w  = (const float*)d_in[16]; const float* s5_bn = (const float*)d_in[17];
    const float* s6_w  = (const float*)d_in[18]; const float* s6_bn = (const float*)d_in[19];
    const float* s7_w  = (const float*)d_in[20]; const float* s7_bn = (const float*)d_in[21];
    const float* pq_w  = (const float*)d_in[22]; const float* pq_b  = (const float*)d_in[23];
    const float* pk_w  = (const float*)d_in[24]; const float* pk_b  = (const float*)d_in[25];
    const float* pv_w  = (const float*)d_in[26]; const float* pv_b  = (const float*)d_in[27];
    const float* gpa   = (const float*)d_in[28];
    const float* gca   = (const float*)d_in[29];

    float *pool, *yca, *ah, *aw, *r, *t1, *cat, *col, *yc, *res;
    float *qb, *kb, *qt, *vb, *attn, *pam, *e, *ac, *cam;
    float *w1f,*b1f,*ws1,*bs1,*ws2,*bs2,*ws3,*bs3,*ws4,*bs4,*ws5,*bs5,*ws6,*bs6,*ws7,*bs7;
    cudaGetSymbolAddress((void**)&pool, g_pool);
    cudaGetSymbolAddress((void**)&yca,  g_yca);
    cudaGetSymbolAddress((void**)&ah,   g_ah);
    cudaGetSymbolAddress((void**)&aw,   g_aw);
    cudaGetSymbolAddress((void**)&r,    g_r);
    cudaGetSymbolAddress((void**)&t1,   g_t1);
    cudaGetSymbolAddress((void**)&cat,  g_cat);
    cudaGetSymbolAddress((void**)&col,  g_col);
    cudaGetSymbolAddress((void**)&yc,   g_yc);
    cudaGetSymbolAddress((void**)&res,  g_res);
    cudaGetSymbolAddress((void**)&qb,   g_q);
    cudaGetSymbolAddress((void**)&kb,   g_kb);
    cudaGetSymbolAddress((void**)&qt,   g_qt);
    cudaGetSymbolAddress((void**)&vb,   g_v);
    cudaGetSymbolAddress((void**)&attn, g_attn);
    cudaGetSymbolAddress((void**)&pam,  g_pam);
    cudaGetSymbolAddress((void**)&e,    g_e);
    cudaGetSymbolAddress((void**)&ac,   g_ac);
    cudaGetSymbolAddress((void**)&cam,  g_cam);
    cudaGetSymbolAddress((void**)&w1f,  g_w1f); cudaGetSymbolAddress((void**)&b1f, g_b1f);
    cudaGetSymbolAddress((void**)&ws1,  g_ws1); cudaGetSymbolAddress((void**)&bs1, g_bs1);
    cudaGetSymbolAddress((void**)&ws2,  g_ws2); cudaGetSymbolAddress((void**)&bs2, g_bs2);
    cudaGetSymbolAddress((void**)&ws3,  g_ws3); cudaGetSymbolAddress((void**)&bs3, g_bs3);
    cudaGetSymbolAddress((void**)&ws4,  g_ws4); cudaGetSymbolAddress((void**)&bs4, g_bs4);
    cudaGetSymbolAddress((void**)&ws5,  g_ws5); cudaGetSymbolAddress((void**)&bs5, g_bs5);
    cudaGetSymbolAddress((void**)&ws6,  g_ws6); cudaGetSymbolAddress((void**)&bs6, g_bs6);
    cudaGetSymbolAddress((void**)&ws7,  g_ws7); cudaGetSymbolAddress((void**)&bs7, g_bs7);

    const int EB = (BATCH*CN + 255)/256;   // elementwise blocks over b,c,h,w

    // ---- fold BN into conv weights ----
    fold_bn_k<<<MIPC,256>>>(ca_w1, ca_bn, ca_b1, w1f, b1f, MIPC, CH);
    fold_bn_k<<<CH,256>>>(s1_w, s1_bn, nullptr, ws1, bs1, CH, CH);
    fold_bn_k<<<CH,256>>>(s2_w, s2_bn, nullptr, ws2, bs2, CH, CH);
    fold_bn_k<<<CH,256>>>(s3_w, s3_bn, nullptr, ws3, bs3, CH, CH*9);
    fold_bn_k<<<CH,256>>>(s4_w, s4_bn, nullptr, ws4, bs4, CH, CH);
    fold_bn_k<<<CH,256>>>(s5_w, s5_bn, nullptr, ws5, bs5, CH, 4*CH);
    fold_bn_k<<<CH,256>>>(s6_w, s6_bn, nullptr, ws6, bs6, CH, CH*9);
    fold_bn_k<<<CH,256>>>(s7_w, s7_bn, nullptr, ws7, bs7, CH, 2*CH);

    // ---- CoordAtt ----
    ca_pool_k<<<dim3(CH,BATCH),64>>>(x, pool);
    gemm_k<2,false><<<dim3(2,1,BATCH),256>>>(w1f, pool, b1f, yca,
        MIPC,128,CH, 128, 0, (long)CH*128, (long)MIPC*128);
    gemm_k<3,false><<<dim3(1,4,BATCH),256>>>(ca_wh, yca,    ca_bh, ah,
        CH,64,MIPC, 128, 0, (long)MIPC*128, (long)CH*64);
    gemm_k<3,false><<<dim3(1,4,BATCH),256>>>(ca_ww, yca+64, ca_bw, aw,
        CH,64,MIPC, 128, 0, (long)MIPC*128, (long)CH*64);
    ca_apply_k<<<EB,256>>>(x, r);

    // ---- SPPCSPC ----
    gemm_k<1,false><<<dim3(64,4,BATCH),256>>>(ws1, r,   bs1, t1,
        CH,NPIX,CH,   NPIX, 0, (long)CN, (long)CN);
    im2col_k<<<(int)(((long)BATCH*2304*NPIX + 255)/256),256>>>(t1, col);
    gemm_k<1,false><<<dim3(64,4,BATCH),256>>>(ws3, col, bs3, t1,
        CH,NPIX,2304, NPIX, 0, (long)2304*NPIX, (long)CN);
    gemm_k<1,false><<<dim3(64,4,BATCH),256>>>(ws4, t1,  bs4, cat,
        CH,NPIX,CH,   NPIX, 0, (long)CN, (long)4*CN);
    maxpool5_k<<<EB,256>>>(cat,        cat+CN,   (long)4*CN);
    maxpool5_k<<<EB,256>>>(cat+CN,     cat+2*CN, (long)4*CN);
    maxpool5_k<<<EB,256>>>(cat+2*CN,   cat+3*CN, (long)4*CN);
    gemm_k<1,false><<<dim3(64,4,BATCH),256>>>(ws5, cat, bs5, t1,
        CH,NPIX,4*CH, NPIX, 0, (long)4*CN, (long)CN);
    im2col_k<<<(int)(((long)BATCH*2304*NPIX + 255)/256),256>>>(t1, col);
    gemm_k<1,false><<<dim3(64,4,BATCH),256>>>(ws6, col, bs6, yc,
        CH,NPIX,2304, NPIX, 0, (long)2304*NPIX, (long)2*CN);
    gemm_k<1,false><<<dim3(64,4,BATCH),256>>>(ws2, r,   bs2, yc+CN,
        CH,NPIX,CH,   NPIX, 0, (long)CN, (long)2*CN);
    gemm_k<1,false><<<dim3(64,4,BATCH),256>>>(ws7, yc,  bs7, res,
        CH,NPIX,2*CH, NPIX, 0, (long)2*CN, (long)CN);

    // ---- PAM ----
    gemm_k<0,false><<<dim3(64,1,BATCH),256>>>(pq_w, res, pq_b, qb,
        CQD,NPIX,CH, NPIX, 0, (long)CN, (long)CQD*NPIX);
    gemm_k<0,false><<<dim3(64,1,BATCH),256>>>(pk_w, res, pk_b, kb,
        CQD,NPIX,CH, NPIX, 0, (long)CN, (long)CQD*NPIX);
    transpose_q_k<<<(BATCH*CQD*NPIX + 255)/256,256>>>(qb, qt);
    gemm_k<0,false><<<dim3(64,4,BATCH),256>>>(pv_w, res, pv_b, vb,
        CH,NPIX,CH, NPIX, 0, (long)CN, (long)CN);
    gemm_k<0,false><<<dim3(64,64,BATCH),256>>>(qt, kb, nullptr, attn,
        NPIX,NPIX,CQD, NPIX, (long)NPIX*CQD, (long)CQD*NPIX, (long)NPIX*NPIX);
    softmax_row_k<<<BATCH*NPIX,256>>>(attn, NPIX);
    gemm_k<0,true><<<dim3(64,4,BATCH),256>>>(vb, attn, nullptr, pam,
        CH,NPIX,NPIX, NPIX, (long)CN, (long)NPIX*NPIX, (long)CN);

    // ---- CAM ----
    gemm_k<0,true><<<dim3(4,4,BATCH),256>>>(res, res, nullptr, e,
        CH,CH,NPIX, NPIX, (long)CN, (long)CN, (long)CH*CH);
    cam_softmax_k<<<BATCH*CH,256>>>(e, ac);
    gemm_k<0,false><<<dim3(64,4,BATCH),256>>>(ac, res, nullptr, cam,
        CH,NPIX,CH, NPIX, (long)CH*CH, (long)CN, (long)CN);

    // ---- combine: res + (gca*cam + res) + (gpa*pam + res) ----
    final_k<<<EB,256>>>(gpa, gca, (float*)d_out);
}

// round 3
// speedup vs baseline: 2.9247x; 2.9247x over previous
#include <cuda_runtime.h>
#include <cstdint>

// Problem constants
#define BATCH 2
#define CH    256
#define NPIX  4096
#define MIPC  8
#define CQD   32
#define CN    (CH*NPIX)

// ===================== static scratch ==================================
__device__ float g_pool[BATCH*CH*128];
__device__ float g_yca [BATCH*MIPC*128];
__device__ float g_ah  [BATCH*CH*64];
__device__ float g_aw  [BATCH*CH*64];
__device__ float g_r   [BATCH*CN];            // NHWC [b][pix][256]
__device__ float g_t1  [BATCH*CN];
__device__ float g_t2  [BATCH*CN];
__device__ float g_cat [(long)BATCH*NPIX*1024];  // NHWC [b][pix][1024]
__device__ float g_mp  [BATCH*CN];
__device__ float g_yc  [(long)BATCH*NPIX*512];   // NHWC [b][pix][512]
__device__ float g_res [BATCH*CN];            // NHWC
__device__ float g_resT[BATCH*CN];            // NCHW
__device__ float g_q   [BATCH*NPIX*CQD];
__device__ float g_k   [BATCH*NPIX*CQD];
__device__ float g_v   [BATCH*CN];            // NCHW
__device__ float g_attn[(long)BATCH*NPIX*NPIX];
__device__ float g_pam [BATCH*CN];            // NCHW
__device__ float g_e   [BATCH*CH*CH];
__device__ float g_ac  [BATCH*CH*CH];
__device__ float g_cam [BATCH*CN];            // NCHW
__device__ float g_w1f[MIPC*CH];   __device__ float g_b1f[MIPC];
__device__ float g_ws1[CH*CH];     __device__ float g_bs1[CH];
__device__ float g_ws2[CH*CH];     __device__ float g_bs2[CH];
__device__ float g_ws3[CH*2304];   __device__ float g_bs3[CH];
__device__ float g_ws4[CH*CH];     __device__ float g_bs4[CH];
__device__ float g_ws5[CH*1024];   __device__ float g_bs5[CH];
__device__ float g_ws6[CH*2304];   __device__ float g_bs6[CH];
__device__ float g_ws7[CH*512];    __device__ float g_bs7[CH];

// ===================== BN fold =========================================
__global__ void fold_bn_k(const float* __restrict__ w, const float* __restrict__ bn,
                          const float* __restrict__ bin,
                          float* __restrict__ wf, float* __restrict__ bf,
                          int O, int Ke, int reorder3)
{
    int o = blockIdx.x;
    float g  = bn[o], be = bn[O+o], mn = bn[2*O+o], vr = bn[3*O+o];
    float s = g * rsqrtf(vr + 1e-5f);
    for (int k = threadIdx.x; k < Ke; k += blockDim.x) {
        float wv;
        if (reorder3) {
            int t = k >> 8, ci = k & 255;      // dst [o][tap][ci]
            wv = w[((long)o*256 + ci)*9 + t];  // src [o][ci][tap]
        } else wv = w[(long)o*Ke + k];
        wf[(long)o*Ke + k] = wv * s;
    }
    if (threadIdx.x == 0) bf[o] = (bin ? bin[o] : 0.f) * s + be - mn * s;
}

// ===================== tf32 mma.sync GEMM ==============================
__device__ __forceinline__ uint32_t f2tf(float f) {
    uint32_t r;
    asm("cvt.rna.tf32.f32 %0, %1;" : "=r"(r) : "f"(f));
    return r;
}
__device__ __forceinline__ uint4 cvt4(float4 v) {
    uint4 o;
    o.x = f2tf(v.x); o.y = f2tf(v.y); o.z = f2tf(v.z); o.w = f2tf(v.w);
    return o;
}
__device__ __forceinline__ void mma_tf32(float c[4], const uint32_t a[4],
                                         const uint32_t b[2]) {
    asm volatile(
        "mma.sync.aligned.m16n8k8.row.col.f32.tf32.tf32.f32 "
        "{%0,%1,%2,%3}, {%4,%5,%6,%7}, {%8,%9}, {%0,%1,%2,%3};"
        : "+f"(c[0]), "+f"(c[1]), "+f"(c[2]), "+f"(c[3])
        : "r"(a[0]), "r"(a[1]), "r"(a[2]), "r"(a[3]), "r"(b[0]), "r"(b[1]));
}

// Row stride 36 words in SMEM (conflict-free fragment LDS: bank=(4g+t)&31)
#define ROWW 36
#define STG_STRIDE (128*ROWW)          // 4608 floats per stage per operand
#define B_BASE (2*STG_STRIDE)          // B after A's two stages
#define SMEM_FLOATS (4*STG_STRIDE)     // 18432 floats = 73728 B

// D[m0..+127][n0..+127] = act( sum_k A[m][k]*B[n][k] + bias )
// A row-major [M][K] K-contig (lda); B row-major [Bn][K] (ldb); C ldc.
// CONV3: A = NHWC activation, k = tap*256+ci, implicit im2col shifts.
template<int ACT, bool CONV3>
__global__ __launch_bounds__(256) void mma_gemm(
    const float* __restrict__ A, const float* __restrict__ B,
    const float* __restrict__ bias, float* __restrict__ C,
    int K, int lda, int ldb, int ldc, int Bn, int ncols, int bias_on_m,
    long sA_, long sB_, long sC_)
{
    extern __shared__ float4 smem4[];
    uint32_t* smu = (uint32_t*)smem4;

    int bz = blockIdx.z;
    A += bz * sA_; B += bz * sB_; C += bz * sC_;
    int m0 = blockIdx.y * 128, n0 = blockIdx.x * 128;
    int tid = threadIdx.x;
    int lane = tid & 31, w = tid >> 5;
    int wm = w >> 1, wn = w & 1;           // 4 x 2 warp grid; warp tile 32x64
    int g = lane >> 2, t = lane & 3;

    float acc[2][8][4] = {};
    uint4 bufA[4], bufB[4];

    auto ldg = [&](int it) {
        int k0 = it * 32;
        if (!CONV3) {
            #pragma unroll
            for (int i = 0; i < 4; i++) {
                int f = i*256 + tid; int m = f >> 3; int c4 = f & 7;
                bufA[i] = cvt4(*(const float4*)(A + (long)(m0+m)*lda + k0 + c4*4));
            }
        } else {
            int tap = k0 >> 8, ci0 = k0 & 255;
            int dy = tap/3 - 1, dx = tap%3 - 1;
            #pragma unroll
            for (int i = 0; i < 4; i++) {
                int f = i*256 + tid; int m = f >> 3; int c4 = f & 7;
                int pix = m0 + m;
                int y = (pix >> 6) + dy, x = (pix & 63) + dx;
                float4 v = make_float4(0.f,0.f,0.f,0.f);
                if ((unsigned)y < 64u && (unsigned)x < 64u)
                    v = *(const float4*)(A + (long)((y<<6)+x)*lda + ci0 + c4*4);
                bufA[i] = cvt4(v);
            }
        }
        #pragma unroll
        for (int i = 0; i < 4; i++) {
            int f = i*256 + tid; int n = f >> 3; int c4 = f & 7;
            float4 v = make_float4(0.f,0.f,0.f,0.f);
            if (n0 + n < Bn)
                v = *(const float4*)(B + (long)(n0+n)*ldb + k0 + c4*4);
            bufB[i] = cvt4(v);
        }
    };
    auto sts = [&](int s) {
        #pragma unroll
        for (int i = 0; i < 4; i++) {
            int f = i*256 + tid; int m = f >> 3; int c4 = f & 7;
            int off = s*STG_STRIDE + m*ROWW + c4*4;
            *(uint4*)(smu + off) = bufA[i];
            *(uint4*)(smu + B_BASE + off) = bufB[i];
        }
    };
    auto compute = [&](int s) {
        #pragma unroll
        for (int ks = 0; ks < 4; ks++) {
            uint32_t af[2][4], bf[8][2];
            #pragma unroll
            for (int mt = 0; mt < 2; mt++) {
                int base = s*STG_STRIDE + (wm*32 + mt*16 + g)*ROWW + ks*8;
                af[mt][0] = smu[base + t];
                af[mt][1] = smu[base + 8*ROWW + t];
                af[mt][2] = smu[base + t + 4];
                af[mt][3] = smu[base + 8*ROWW + t + 4];
            }
            #pragma unroll
            for (int nt = 0; nt < 8; nt++) {
                int base = B_BASE + s*STG_STRIDE + (wn*64 + nt*8 + g)*ROWW + ks*8;
                bf[nt][0] = smu[base + t];
                bf[nt][1] = smu[base + t + 4];
            }
            #pragma unroll
            for (int mt = 0; mt < 2; mt++)
                #pragma unroll
                for (int nt = 0; nt < 8; nt++)
                    mma_tf32(acc[mt][nt], af[mt], bf[nt]);
        }
    };

    int T = K >> 5;
    ldg(0);
    sts(0);
    __syncthreads();
    for (int it = 0; it < T; it++) {
        if (it + 1 < T) ldg(it + 1);
        compute(it & 1);
        if (it + 1 < T) {
            __syncthreads();
            sts((it + 1) & 1);
            __syncthreads();
        }
    }

    // epilogue
    int valid = ncols - n0; if (valid > 128) valid = 128;
    #pragma unroll
    for (int mt = 0; mt < 2; mt++) {
        #pragma unroll
        for (int half = 0; half < 2; half++) {
            int m = m0 + wm*32 + mt*16 + g + half*8;
            float bm = (bias && bias_on_m) ? bias[m] : 0.f;
            float* Crow = C + (long)m*ldc + n0;
            #pragma unroll
            for (int nt = 0; nt < 8; nt++) {
                int nl = wn*64 + nt*8 + 2*t;
                if (nl >= valid) continue;
                float v0 = acc[mt][nt][half*2 + 0] + bm;
                float v1 = acc[mt][nt][half*2 + 1] + bm;
                if (bias && !bias_on_m) { v0 += bias[n0+nl]; v1 += bias[n0+nl+1]; }
                if (ACT == 1) {
                    v0 = v0 / (1.f + __expf(-v0));
                    v1 = v1 / (1.f + __expf(-v1));
                }
                *(float2*)(Crow + nl) = make_float2(v0, v1);
            }
        }
    }
}

// ===================== small FMA GEMM (CoordAtt only) ==================
template<int ACT>
__global__ __launch_bounds__(256) void gemm_small(
    const float* __restrict__ A, const float* __restrict__ B,
    const float* __restrict__ bias, float* __restrict__ C,
    int M, int N, int K, int ldb, long sA, long sB, long sC)
{
    int b = blockIdx.z;
    A += (long)b*sA; B += (long)b*sB; C += (long)b*sC;
    int m0 = blockIdx.y*64, n0 = blockIdx.x*64;
    __shared__ float As[16][64], Bs[16][65];
    int tid = threadIdx.x, tx = tid & 15, ty = tid >> 4;
    float acc[4][4] = {};
    for (int k0 = 0; k0 < K; k0 += 16) {
        int i = tid >> 2, jb = (tid & 3)*4, mI = m0 + i;
        #pragma unroll
        for (int j = 0; j < 4; j++) {
            int k = k0 + jb + j;
            As[jb+j][i] = (mI < M && k < K) ? A[(long)mI*K + k] : 0.f;
        }
        int jr = tid >> 4, nb = (tid & 15)*4, k = k0 + jr;
        #pragma unroll
        for (int n = 0; n < 4; n++) {
            int nn = n0 + nb + n;
            Bs[jr][nb+n] = (k < K && nn < N) ? B[(long)k*ldb + nn] : 0.f;
        }
        __syncthreads();
        #pragma unroll
        for (int j = 0; j < 16; j++) {
            float a[4], bb[4];
            #pragma unroll
            for (int i2 = 0; i2 < 4; i2++) a[i2]  = As[j][ty*4+i2];
            #pragma unroll
            for (int i2 = 0; i2 < 4; i2++) bb[i2] = Bs[j][tx*4+i2];
            #pragma unroll
            for (int i2 = 0; i2 < 4; i2++)
                #pragma unroll
                for (int jj = 0; jj < 4; jj++) acc[i2][jj] += a[i2]*bb[jj];
        }
        __syncthreads();
    }
    #pragma unroll
    for (int i = 0; i < 4; i++) {
        int mI = m0 + ty*4 + i;
        if (mI >= M) continue;
        float bv = bias ? bias[mI] : 0.f;
        #pragma unroll
        for (int jj = 0; jj < 4; jj++) {
            int n = n0 + tx*4 + jj;
            if (n >= N) continue;
            float v = acc[i][jj] + bv;
            if (ACT == 2) { float tq = fminf(fmaxf(v+3.f,0.f),6.f); v = v*tq*(1.f/6.f); }
            else if (ACT == 3) v = 1.f/(1.f+__expf(-v));
            C[(long)mI*N + n] = v;
        }
    }
}

// ===================== CoordAtt glue ==================================
__global__ void ca_pool_k(const float* __restrict__ x, float* __restrict__ pool)
{
    int c = blockIdx.x, b = blockIdx.y, t = threadIdx.x;
    const float* p = x + ((long)b*CH + c)*NPIX;
    float sh = 0.f, sw = 0.f;
    for (int i = 0; i < 64; i++) sh += p[t*64 + i];
    for (int i = 0; i < 64; i++) sw += p[i*64 + t];
    float* o = pool + ((long)b*CH + c)*128;
    o[t] = sh*(1.f/64.f); o[64+t] = sw*(1.f/64.f);
}

__global__ void ca_apply_k(const float* __restrict__ x, float* __restrict__ r)
{
    long i = blockIdx.x*256L + threadIdx.x;
    if (i >= (long)BATCH*CN) return;
    int c = (int)(i & 255); long t = i >> 8;
    int pix = (int)(t & 4095); int b = (int)(t >> 12);
    long bc = (long)b*CH + c;
    int y = pix >> 6, xx = pix & 63;
    r[i] = x[(long)b*CN + (long)c*NPIX + pix] * g_aw[bc*64+xx] * g_ah[bc*64+y];
}

// ===================== separable maxpool (NHWC, 5-wide) ===============
__global__ void mp_h_k(const float* __restrict__ src, float* __restrict__ tmp)
{
    long i = blockIdx.x*256L + threadIdx.x;
    if (i >= (long)BATCH*CN) return;
    int c = (int)(i & 255); long t = i >> 8;
    int pix = (int)(t & 4095); int b = (int)(t >> 12);
    int y = pix >> 6, x = pix & 63;
    const float* s = src + (long)b*NPIX*1024;
    float m = -3.4e38f;
    #pragma unroll
    for (int d = -2; d <= 2; d++) {
        int xx = x + d;
        if ((unsigned)xx < 64u) m = fmaxf(m, s[(long)((y<<6)+xx)*1024 + c]);
    }
    tmp[(long)b*CN + (long)pix*256 + c] = m;
}
__global__ void mp_v_k(const float* __restrict__ tmp, float* __restrict__ dst)
{
    long i = blockIdx.x*256L + threadIdx.x;
    if (i >= (long)BATCH*CN) return;
    int c = (int)(i & 255); long t = i >> 8;
    int pix = (int)(t & 4095); int b = (int)(t >> 12);
    int y = pix >> 6, x = pix & 63;
    const float* s = tmp + (long)b*CN;
    float m = -3.4e38f;
    #pragma unroll
    for (int d = -2; d <= 2; d++) {
        int yy = y + d;
        if ((unsigned)yy < 64u) m = fmaxf(m, s[(long)((yy<<6)+x)*256 + c]);
    }
    dst[(long)b*NPIX*1024 + (long)pix*1024 + c] = m;
}

// ===================== PAM softmax (rows of 4096) =====================
__global__ void softmax_row_k(float* __restrict__ a)
{
    float* p = a + (long)blockIdx.x * 4096;
    int t = threadIdx.x;
    __shared__ float red[256];
    float v[16];
    #pragma unroll
    for (int i = 0; i < 16; i++) v[i] = p[t + i*256];
    float mx = v[0];
    #pragma unroll
    for (int i = 1; i < 16; i++) mx = fmaxf(mx, v[i]);
    red[t] = mx; __syncthreads();
    for (int s = 128; s > 0; s >>= 1) { if (t < s) red[t] = fmaxf(red[t], red[t+s]); __syncthreads(); }
    mx = red[0]; __syncthreads();
    float sum = 0.f;
    #pragma unroll
    for (int i = 0; i < 16; i++) { v[i] = __expf(v[i] - mx); sum += v[i]; }
    red[t] = sum; __syncthreads();
    for (int s = 128; s > 0; s >>= 1) { if (t < s) red[t] += red[t+s]; __syncthreads(); }
    float inv = 1.f / red[0];
    #pragma unroll
    for (int i = 0; i < 16; i++) p[t + i*256] = v[i] * inv;
}

// ===================== CAM softmax =====================================
__global__ void cam_softmax_k(const float* __restrict__ e, float* __restrict__ ac)
{
    long row = blockIdx.x;
    const float* p = e + row*256;
    int t = threadIdx.x;
    __shared__ float sm[256];
    float v = p[t];
    sm[t] = v; __syncthreads();
    for (int s = 128; s > 0; s >>= 1) { if (t < s) sm[t] = fmaxf(sm[t], sm[t+s]); __syncthreads(); }
    float rowmax = sm[0]; __syncthreads();
    float z = rowmax - v;
    sm[t] = z; __syncthreads();
    for (int s = 128; s > 0; s >>= 1) { if (t < s) sm[t] = fmaxf(sm[t], sm[t+s]); __syncthreads(); }
    float zm = sm[0]; __syncthreads();
    float pe = __expf(z - zm);
    sm[t] = pe; __syncthreads();
    for (int s = 128; s > 0; s >>= 1) { if (t < s) sm[t] += sm[t+s]; __syncthreads(); }
    ac[row*256 + t] = pe / sm[0];
}

// ===================== tiled transpose NHWC -> NCHW ====================
__global__ void transpose_k(const float* __restrict__ src, float* __restrict__ dst)
{
    __shared__ float s[32][33];
    int b = blockIdx.z;
    int p0 = blockIdx.x*32, c0 = blockIdx.y*32;
    int tx = threadIdx.x, ty = threadIdx.y;  // 32 x 8
    const float* S = src + (long)b*CN;
    float* D = dst + (long)b*CN;
    #pragma unroll
    for (int j = 0; j < 32; j += 8)
        s[ty+j][tx] = S[(long)(p0+ty+j)*256 + c0+tx];
    __syncthreads();
    #pragma unroll
    for (int j = 0; j < 32; j += 8)
        D[(long)(c0+ty+j)*4096 + p0+tx] = s[tx][ty+j];
}

// ===================== final combine (all NCHW) ========================
__global__ void final_k(const float* __restrict__ gpa, const float* __restrict__ gca,
                        float* __restrict__ out)
{
    long i = blockIdx.x*256L + threadIdx.x;
    if (i >= (long)BATCH*CN) return;
    out[i] = 3.f*g_resT[i] + gpa[0]*g_pam[i] + gca[0]*g_cam[i];
}

// ======================================================================
extern "C" void kernel_launch(void* const* d_in, const int* in_sizes, int n_in,
                              void* d_out, int out_size)
{
    const float* x     = (const float*)d_in[0];
    const float* ca_w1 = (const float*)d_in[1];
    const float* ca_b1 = (const float*)d_in[2];
    const float* ca_bn = (const float*)d_in[3];
    const float* ca_wh = (const float*)d_in[4];
    const float* ca_bh = (const float*)d_in[5];
    const float* ca_ww = (const float*)d_in[6];
    const float* ca_bw = (const float*)d_in[7];
    const float* s1_w  = (const float*)d_in[8];  const float* s1_bn = (const float*)d_in[9];
    const float* s2_w  = (const float*)d_in[10]; const float* s2_bn = (const float*)d_in[11];
    const float* s3_w  = (const float*)d_in[12]; const float* s3_bn = (const float*)d_in[13];
    const float* s4_w  = (const float*)d_in[14]; const float* s4_bn = (const float*)d_in[15];
    const float* s5_w  = (const float*)d_in[16]; const float* s5_bn = (const float*)d_in[17];
    const float* s6_w  = (const float*)d_in[18]; const float* s6_bn = (const float*)d_in[19];
    const float* s7_w  = (const float*)d_in[20]; const float* s7_bn = (const float*)d_in[21];
    const float* pq_w  = (const float*)d_in[22]; const float* pq_b  = (const float*)d_in[23];
    const float* pk_w  = (const float*)d_in[24]; const float* pk_b  = (const float*)d_in[25];
    const float* pv_w  = (const float*)d_in[26]; const float* pv_b  = (const float*)d_in[27];
    const float* gpa   = (const float*)d_in[28];
    const float* gca   = (const float*)d_in[29];

    float *pool,*yca,*ah,*aw,*r,*t1,*t2,*cat,*mp,*yc,*res,*resT,*qb,*kb,*vb,*attn,*pam,*e,*ac,*cam;
    float *w1f,*b1f,*ws1,*bs1,*ws2,*bs2,*ws3,*bs3,*ws4,*bs4,*ws5,*bs5,*ws6,*bs6,*ws7,*bs7;
    cudaGetSymbolAddress((void**)&pool, g_pool);  cudaGetSymbolAddress((void**)&yca, g_yca);
    cudaGetSymbolAddress((void**)&ah, g_ah);      cudaGetSymbolAddress((void**)&aw, g_aw);
    cudaGetSymbolAddress((void**)&r, g_r);        cudaGetSymbolAddress((void**)&t1, g_t1);
    cudaGetSymbolAddress((void**)&t2, g_t2);      cudaGetSymbolAddress((void**)&cat, g_cat);
    cudaGetSymbolAddress((void**)&mp, g_mp);      cudaGetSymbolAddress((void**)&yc, g_yc);
    cudaGetSymbolAddress((void**)&res, g_res);    cudaGetSymbolAddress((void**)&resT, g_resT);
    cudaGetSymbolAddress((void**)&qb, g_q);       cudaGetSymbolAddress((void**)&kb, g_k);
    cudaGetSymbolAddress((void**)&vb, g_v);       cudaGetSymbolAddress((void**)&attn, g_attn);
    cudaGetSymbolAddress((void**)&pam, g_pam);    cudaGetSymbolAddress((void**)&e, g_e);
    cudaGetSymbolAddress((void**)&ac, g_ac);      cudaGetSymbolAddress((void**)&cam, g_cam);
    cudaGetSymbolAddress((void**)&w1f, g_w1f);    cudaGetSymbolAddress((void**)&b1f, g_b1f);
    cudaGetSymbolAddress((void**)&ws1, g_ws1);    cudaGetSymbolAddress((void**)&bs1, g_bs1);
    cudaGetSymbolAddress((void**)&ws2, g_ws2);    cudaGetSymbolAddress((void**)&bs2, g_bs2);
    cudaGetSymbolAddress((void**)&ws3, g_ws3);    cudaGetSymbolAddress((void**)&bs3, g_bs3);
    cudaGetSymbolAddress((void**)&ws4, g_ws4);    cudaGetSymbolAddress((void**)&bs4, g_bs4);
    cudaGetSymbolAddress((void**)&ws5, g_ws5);    cudaGetSymbolAddress((void**)&bs5, g_bs5);
    cudaGetSymbolAddress((void**)&ws6, g_ws6);    cudaGetSymbolAddress((void**)&bs6, g_bs6);
    cudaGetSymbolAddress((void**)&ws7, g_ws7);    cudaGetSymbolAddress((void**)&bs7, g_bs7);

    const int SMEMSZ = SMEM_FLOATS * 4;   // 73728 B
    cudaFuncSetAttribute(mma_gemm<0,false>, cudaFuncAttributeMaxDynamicSharedMemorySize, SMEMSZ);
    cudaFuncSetAttribute(mma_gemm<1,false>, cudaFuncAttributeMaxDynamicSharedMemorySize, SMEMSZ);
    cudaFuncSetAttribute(mma_gemm<1,true>,  cudaFuncAttributeMaxDynamicSharedMemorySize, SMEMSZ);

    const int EB = (BATCH*CN + 255)/256;

    // ---- fold BN ----
    fold_bn_k<<<MIPC,256>>>(ca_w1, ca_bn, ca_b1, w1f, b1f, MIPC, CH, 0);
    fold_bn_k<<<CH,256>>>(s1_w, s1_bn, nullptr, ws1, bs1, CH, CH, 0);
    fold_bn_k<<<CH,256>>>(s2_w, s2_bn, nullptr, ws2, bs2, CH, CH, 0);
    fold_bn_k<<<CH,256>>>(s3_w, s3_bn, nullptr, ws3, bs3, CH, 2304, 1);
    fold_bn_k<<<CH,256>>>(s4_w, s4_bn, nullptr, ws4, bs4, CH, CH, 0);
    fold_bn_k<<<CH,256>>>(s5_w, s5_bn, nullptr, ws5, bs5, CH, 1024, 0);
    fold_bn_k<<<CH,256>>>(s6_w, s6_bn, nullptr, ws6, bs6, CH, 2304, 1);
    fold_bn_k<<<CH,256>>>(s7_w, s7_bn, nullptr, ws7, bs7, CH, 512, 0);

    // ---- CoordAtt (tiny, FMA path) ----
    ca_pool_k<<<dim3(CH,BATCH),64>>>(x, pool);
    gemm_small<2><<<dim3(2,1,BATCH),256>>>(w1f, pool, b1f, yca,
        MIPC,128,CH, 128, 0, (long)CH*128, (long)MIPC*128);
    gemm_small<3><<<dim3(1,4,BATCH),256>>>(ca_wh, yca,    ca_bh, ah,
        CH,64,MIPC, 128, 0, (long)MIPC*128, (long)CH*64);
    gemm_small<3><<<dim3(1,4,BATCH),256>>>(ca_ww, yca+64, ca_bw, aw,
        CH,64,MIPC, 128, 0, (long)MIPC*128, (long)CH*64);
    ca_apply_k<<<EB,256>>>(x, r);

    // ---- SPPCSPC (NHWC, tensor cores via mma.sync tf32) ----
    mma_gemm<1,false><<<dim3(2,32,BATCH),256,SMEMSZ>>>(r, ws1, bs1, t1,
        256,256,256,256, 256,256,0, (long)CN,0,(long)CN);
    mma_gemm<1,true ><<<dim3(2,32,BATCH),256,SMEMSZ>>>(t1, ws3, bs3, t2,
        2304,256,2304,256, 256,256,0, (long)CN,0,(long)CN);
    mma_gemm<1,false><<<dim3(2,32,BATCH),256,SMEMSZ>>>(t2, ws4, bs4, cat,
        256,256,256,1024, 256,256,0, (long)CN,0,(long)NPIX*1024);
    mp_h_k<<<EB,256>>>(cat,       mp); mp_v_k<<<EB,256>>>(mp, cat+256);
    mp_h_k<<<EB,256>>>(cat+256,   mp); mp_v_k<<<EB,256>>>(mp, cat+512);
    mp_h_k<<<EB,256>>>(cat+512,   mp); mp_v_k<<<EB,256>>>(mp, cat+768);
    mma_gemm<1,false><<<dim3(2,32,BATCH),256,SMEMSZ>>>(cat, ws5, bs5, t1,
        1024,1024,1024,256, 256,256,0, (long)NPIX*1024,0,(long)CN);
    mma_gemm<1,true ><<<dim3(2,32,BATCH),256,SMEMSZ>>>(t1, ws6, bs6, yc,
        2304,256,2304,512, 256,256,0, (long)CN,0,(long)NPIX*512);
    mma_gemm<1,false><<<dim3(2,32,BATCH),256,SMEMSZ>>>(r, ws2, bs2, yc+256,
        256,256,256,512, 256,256,0, (long)CN,0,(long)NPIX*512);
    mma_gemm<1,false><<<dim3(2,32,BATCH),256,SMEMSZ>>>(yc, ws7, bs7, res,
        512,512,512,256, 256,256,0, (long)NPIX*512,0,(long)CN);

    // ---- PAM ----
    mma_gemm<0,false><<<dim3(1,32,BATCH),256,SMEMSZ>>>(res, pq_w, pq_b, qb,
        256,256,256,CQD, CQD,CQD,0, (long)CN,0,(long)NPIX*CQD);
    mma_gemm<0,false><<<dim3(1,32,BATCH),256,SMEMSZ>>>(res, pk_w, pk_b, kb,
        256,256,256,CQD, CQD,CQD,0, (long)CN,0,(long)NPIX*CQD);
    mma_gemm<0,false><<<dim3(32,2,BATCH),256,SMEMSZ>>>(pv_w, res, pv_b, vb,
        256,256,256,NPIX, NPIX,NPIX,1, 0,(long)CN,(long)CN);
    mma_gemm<0,false><<<dim3(32,32,BATCH),256,SMEMSZ>>>(qb, kb, nullptr, attn,
        CQD,CQD,CQD,NPIX, NPIX,NPIX,0, (long)NPIX*CQD,(long)NPIX*CQD,(long)NPIX*NPIX);
    softmax_row_k<<<BATCH*NPIX,256>>>(attn);
    mma_gemm<0,false><<<dim3(32,2,BATCH),256,SMEMSZ>>>(vb, attn, nullptr, pam,
        NPIX,NPIX,NPIX,NPIX, NPIX,NPIX,0, (long)CN,(long)NPIX*NPIX,(long)CN);

    // ---- CAM ----
    transpose_k<<<dim3(128,8,BATCH),dim3(32,8)>>>(res, resT);
    mma_gemm<0,false><<<dim3(2,2,BATCH),256,SMEMSZ>>>(resT, resT, nullptr, e,
        NPIX,NPIX,NPIX,256, 256,256,0, (long)CN,(long)CN,(long)CH*CH);
    cam_softmax_k<<<BATCH*CH,256>>>(e, ac);
    mma_gemm<0,false><<<dim3(32,2,BATCH),256,SMEMSZ>>>(ac, res, nullptr, cam,
        256,256,256,NPIX, NPIX,NPIX,0, (long)CH*CH,(long)CN,(long)CN);

    // ---- combine ----
    final_k<<<EB,256>>>(gpa, gca, (float*)d_out);
}

// round 4
// speedup vs baseline: 3.4563x; 1.1818x over previous
#include <cuda_runtime.h>
#include <cstdint>

// Problem constants
#define BATCH 2
#define CH    256
#define NPIX  4096
#define MIPC  8
#define CQD   32
#define CN    (CH*NPIX)
#define ESPLIT 8

// ===================== static scratch ==================================
__device__ float g_pool[BATCH*CH*128];
__device__ float g_yca [BATCH*MIPC*128];
__device__ float g_ah  [BATCH*CH*64];
__device__ float g_aw  [BATCH*CH*64];
__device__ float g_r   [BATCH*CN];            // NHWC [b][pix][256]
__device__ float g_t1  [BATCH*CN];
__device__ float g_t2  [BATCH*CN];
__device__ float g_cat [(long)BATCH*NPIX*1024];  // NHWC [b][pix][1024]
__device__ float g_mp  [BATCH*CN];
__device__ float g_yc  [(long)BATCH*NPIX*512];   // NHWC [b][pix][512]
__device__ float g_res [BATCH*CN];            // NHWC
__device__ float g_resT[BATCH*CN];            // NCHW
__device__ float g_qk  [BATCH*NPIX*64];       // [b][pix][64]: q|k
__device__ float g_v   [BATCH*CN];            // NCHW
__device__ float g_attn[(long)BATCH*NPIX*NPIX];
__device__ float g_pam [BATCH*CN];            // NCHW
__device__ float g_e   [BATCH*CH*CH];
__device__ float g_epart[BATCH*ESPLIT*CH*CH];
__device__ float g_ac  [BATCH*CH*CH];
__device__ float g_w1f[MIPC*CH];   __device__ float g_b1f[MIPC];
__device__ float g_ws1[CH*CH];     __device__ float g_bs1[CH];
__device__ float g_ws2[CH*CH];     __device__ float g_bs2[CH];
__device__ float g_ws3[CH*2304];   __device__ float g_bs3[CH];
__device__ float g_ws4[CH*CH];     __device__ float g_bs4[CH];
__device__ float g_ws5[CH*1024];   __device__ float g_bs5[CH];
__device__ float g_ws6[CH*2304];   __device__ float g_bs6[CH];
__device__ float g_ws7[CH*512];    __device__ float g_bs7[CH];
__device__ float g_wqk[64*CH];     __device__ float g_bqk[64];

// ===================== merged BN fold (all jobs, 1 launch) =============
struct FoldArgs {
    const float* w[8]; const float* bn[8]; const float* bin[8];
    float* wf[8]; float* bf[8];
    int O[8]; int Ke[8]; int ro[8];
    const float *pq_w, *pq_b, *pk_w, *pk_b;
    float *qkw, *qkb;
};

__global__ void fold_all_k(FoldArgs a)
{
    int j = blockIdx.y, o = blockIdx.x;
    if (j == 8) {  // qk weight/bias concat
        if (o >= 64) return;
        const float* src = (o < 32) ? (a.pq_w + (long)o*256)
                                    : (a.pk_w + (long)(o-32)*256);
        for (int k = threadIdx.x; k < 256; k += blockDim.x)
            a.qkw[(long)o*256 + k] = src[k];
        if (threadIdx.x == 0)
            a.qkb[o] = (o < 32) ? a.pq_b[o] : a.pk_b[o-32];
        return;
    }
    int O = a.O[j];
    if (o >= O) return;
    const float* bn = a.bn[j];
    float g  = bn[o], be = bn[O+o], mn = bn[2*O+o], vr = bn[3*O+o];
    float s = g * rsqrtf(vr + 1e-5f);
    int Ke = a.Ke[j];
    const float* w = a.w[j];
    float* wf = a.wf[j];
    if (a.ro[j]) {
        for (int k = threadIdx.x; k < Ke; k += blockDim.x) {
            int t = k >> 8, ci = k & 255;
            wf[(long)o*Ke + k] = w[((long)o*256 + ci)*9 + t] * s;
        }
    } else {
        for (int k = threadIdx.x; k < Ke; k += blockDim.x)
            wf[(long)o*Ke + k] = w[(long)o*Ke + k] * s;
    }
    if (threadIdx.x == 0)
        a.bf[j][o] = (a.bin[j] ? a.bin[j][o] : 0.f) * s + be - mn * s;
}

// ===================== tf32 mma.sync GEMM ==============================
__device__ __forceinline__ uint32_t f2tf(float f) {
    uint32_t r;
    asm("cvt.rna.tf32.f32 %0, %1;" : "=r"(r) : "f"(f));
    return r;
}
__device__ __forceinline__ uint4 cvt4(float4 v) {
    uint4 o;
    o.x = f2tf(v.x); o.y = f2tf(v.y); o.z = f2tf(v.z); o.w = f2tf(v.w);
    return o;
}
__device__ __forceinline__ void mma_tf32(float c[4], const uint32_t a[4],
                                         const uint32_t b[2]) {
    asm volatile(
        "mma.sync.aligned.m16n8k8.row.col.f32.tf32.tf32.f32 "
        "{%0,%1,%2,%3}, {%4,%5,%6,%7}, {%8,%9}, {%0,%1,%2,%3};"
        : "+f"(c[0]), "+f"(c[1]), "+f"(c[2]), "+f"(c[3])
        : "r"(a[0]), "r"(a[1]), "r"(a[2]), "r"(a[3]), "r"(b[0]), "r"(b[1]));
}

#define ROWW 36
#define STG_STRIDE (128*ROWW)
#define B_BASE (2*STG_STRIDE)
#define SMEM_FLOATS (4*STG_STRIDE)

// D[m0..+127][n0..+127] = act( sum_k A[m][k]*B[n][k] + bias )
// ACT: 0 none, 1 SiLU, 4 final-combine (3*f1 + gam1*f2 + gam2*acc)
template<int ACT, bool CONV3>
__global__ __launch_bounds__(256) void mma_gemm(
    const float* __restrict__ A, const float* __restrict__ B,
    const float* __restrict__ bias, float* __restrict__ C,
    int K, int lda, int ldb, int ldc, int Bn, int ncols, int bias_on_m,
    long sA_, long sB_, long sC_,
    int nsplit = 1,
    const float* __restrict__ f1 = nullptr, const float* __restrict__ f2 = nullptr,
    const float* __restrict__ gam1 = nullptr, const float* __restrict__ gam2 = nullptr)
{
    extern __shared__ float4 smem4[];
    uint32_t* smu = (uint32_t*)smem4;

    int bz = blockIdx.z;
    int batch = bz, slice = 0;
    if (nsplit > 1) { batch = bz / nsplit; slice = bz - batch * nsplit; }
    A += batch * sA_ + (long)slice * K;
    B += batch * sB_ + (long)slice * K;
    C += (long)bz * sC_;
    if (ACT == 4) { f1 += (long)batch * CN; f2 += (long)batch * CN; }
    float gg1 = 0.f, gg2 = 0.f;
    if (ACT == 4) { gg1 = gam1[0]; gg2 = gam2[0]; }

    int m0 = blockIdx.y * 128, n0 = blockIdx.x * 128;
    int tid = threadIdx.x;
    int lane = tid & 31, w = tid >> 5;
    int wm = w >> 1, wn = w & 1;
    int g = lane >> 2, t = lane & 3;

    float acc[2][8][4] = {};
    uint4 bufA[4], bufB[4];

    auto ldg = [&](int it) {
        int k0 = it * 32;
        if (!CONV3) {
            #pragma unroll
            for (int i = 0; i < 4; i++) {
                int f = i*256 + tid; int m = f >> 3; int c4 = f & 7;
                bufA[i] = cvt4(*(const float4*)(A + (long)(m0+m)*lda + k0 + c4*4));
            }
        } else {
            int tap = k0 >> 8, ci0 = k0 & 255;
            int dy = tap/3 - 1, dx = tap%3 - 1;
            #pragma unroll
            for (int i = 0; i < 4; i++) {
                int f = i*256 + tid; int m = f >> 3; int c4 = f & 7;
                int pix = m0 + m;
                int y = (pix >> 6) + dy, x = (pix & 63) + dx;
                float4 v = make_float4(0.f,0.f,0.f,0.f);
                if ((unsigned)y < 64u && (unsigned)x < 64u)
                    v = *(const float4*)(A + (long)((y<<6)+x)*lda + ci0 + c4*4);
                bufA[i] = cvt4(v);
            }
        }
        #pragma unroll
        for (int i = 0; i < 4; i++) {
            int f = i*256 + tid; int n = f >> 3; int c4 = f & 7;
            float4 v = make_float4(0.f,0.f,0.f,0.f);
            if (n0 + n < Bn)
                v = *(const float4*)(B + (long)(n0+n)*ldb + k0 + c4*4);
            bufB[i] = cvt4(v);
        }
    };
    auto sts = [&](int s) {
        #pragma unroll
        for (int i = 0; i < 4; i++) {
            int f = i*256 + tid; int m = f >> 3; int c4 = f & 7;
            int off = s*STG_STRIDE + m*ROWW + c4*4;
            *(uint4*)(smu + off) = bufA[i];
            *(uint4*)(smu + B_BASE + off) = bufB[i];
        }
    };
    auto compute = [&](int s) {
        #pragma unroll
        for (int ks = 0; ks < 4; ks++) {
            uint32_t af[2][4], bf[8][2];
            #pragma unroll
            for (int mt = 0; mt < 2; mt++) {
                int base = s*STG_STRIDE + (wm*32 + mt*16 + g)*ROWW + ks*8;
                af[mt][0] = smu[base + t];
                af[mt][1] = smu[base + 8*ROWW + t];
                af[mt][2] = smu[base + t + 4];
                af[mt][3] = smu[base + 8*ROWW + t + 4];
            }
            #pragma unroll
            for (int nt = 0; nt < 8; nt++) {
                int base = B_BASE + s*STG_STRIDE + (wn*64 + nt*8 + g)*ROWW + ks*8;
                bf[nt][0] = smu[base + t];
                bf[nt][1] = smu[base + t + 4];
            }
            #pragma unroll
            for (int mt = 0; mt < 2; mt++)
                #pragma unroll
                for (int nt = 0; nt < 8; nt++)
                    mma_tf32(acc[mt][nt], af[mt], bf[nt]);
        }
    };

    int T = K >> 5;
    ldg(0);
    sts(0);
    __syncthreads();
    for (int it = 0; it < T; it++) {
        if (it + 1 < T) ldg(it + 1);
        compute(it & 1);
        if (it + 1 < T) {
            __syncthreads();
            sts((it + 1) & 1);
            __syncthreads();
        }
    }

    // epilogue
    int valid = ncols - n0; if (valid > 128) valid = 128;
    #pragma unroll
    for (int mt = 0; mt < 2; mt++) {
        #pragma unroll
        for (int half = 0; half < 2; half++) {
            int m = m0 + wm*32 + mt*16 + g + half*8;
            float bm = (bias && bias_on_m) ? bias[m] : 0.f;
            long base = (long)m*ldc + n0;
            float* Crow = C + base;
            #pragma unroll
            for (int nt = 0; nt < 8; nt++) {
                int nl = wn*64 + nt*8 + 2*t;
                if (nl >= valid) continue;
                float v0 = acc[mt][nt][half*2 + 0] + bm;
                float v1 = acc[mt][nt][half*2 + 1] + bm;
                if (bias && !bias_on_m) { v0 += bias[n0+nl]; v1 += bias[n0+nl+1]; }
                if (ACT == 1) {
                    v0 = v0 / (1.f + __expf(-v0));
                    v1 = v1 / (1.f + __expf(-v1));
                } else if (ACT == 4) {
                    float2 r1 = *(const float2*)(f1 + base + nl);
                    float2 r2 = *(const float2*)(f2 + base + nl);
                    v0 = 3.f*r1.x + gg1*r2.x + gg2*v0;
                    v1 = 3.f*r1.y + gg1*r2.y + gg2*v1;
                }
                *(float2*)(Crow + nl) = make_float2(v0, v1);
            }
        }
    }
}

// ===================== small FMA GEMM (CoordAtt yca only) =============
template<int ACT>
__global__ __launch_bounds__(256) void gemm_small(
    const float* __restrict__ A, const float* __restrict__ B,
    const float* __restrict__ bias, float* __restrict__ C,
    int M, int N, int K, int ldb, long sA, long sB, long sC)
{
    int b = blockIdx.z;
    A += (long)b*sA; B += (long)b*sB; C += (long)b*sC;
    int m0 = blockIdx.y*64, n0 = blockIdx.x*64;
    __shared__ float As[16][64], Bs[16][65];
    int tid = threadIdx.x, tx = tid & 15, ty = tid >> 4;
    float acc[4][4] = {};
    for (int k0 = 0; k0 < K; k0 += 16) {
        int i = tid >> 2, jb = (tid & 3)*4, mI = m0 + i;
        #pragma unroll
        for (int j = 0; j < 4; j++) {
            int k = k0 + jb + j;
            As[jb+j][i] = (mI < M && k < K) ? A[(long)mI*K + k] : 0.f;
        }
        int jr = tid >> 4, nb = (tid & 15)*4, k = k0 + jr;
        #pragma unroll
        for (int n = 0; n < 4; n++) {
            int nn = n0 + nb + n;
            Bs[jr][nb+n] = (k < K && nn < N) ? B[(long)k*ldb + nn] : 0.f;
        }
        __syncthreads();
        #pragma unroll
        for (int j = 0; j < 16; j++) {
            float a[4], bb[4];
            #pragma unroll
            for (int i2 = 0; i2 < 4; i2++) a[i2]  = As[j][ty*4+i2];
            #pragma unroll
            for (int i2 = 0; i2 < 4; i2++) bb[i2] = Bs[j][tx*4+i2];
            #pragma unroll
            for (int i2 = 0; i2 < 4; i2++)
                #pragma unroll
                for (int jj = 0; jj < 4; jj++) acc[i2][jj] += a[i2]*bb[jj];
        }
        __syncthreads();
    }
    #pragma unroll
    for (int i = 0; i < 4; i++) {
        int mI = m0 + ty*4 + i;
        if (mI >= M) continue;
        float bv = bias ? bias[mI] : 0.f;
        #pragma unroll
        for (int jj = 0; jj < 4; jj++) {
            int n = n0 + tx*4 + jj;
            if (n >= N) continue;
            float v = acc[i][jj] + bv;
            if (ACT == 2) { float tq = fminf(fmaxf(v+3.f,0.f),6.f); v = v*tq*(1.f/6.f); }
            C[(long)mI*N + n] = v;
        }
    }
}

// ===================== CoordAtt glue ==================================
__global__ void ca_pool_k(const float* __restrict__ x, float* __restrict__ pool)
{
    int c = blockIdx.x, b = blockIdx.y, t = threadIdx.x;
    const float* p = x + ((long)b*CH + c)*NPIX;
    float sh = 0.f, sw = 0.f;
    for (int i = 0; i < 64; i++) sh += p[t*64 + i];
    for (int i = 0; i < 64; i++) sw += p[i*64 + t];
    float* o = pool + ((long)b*CH + c)*128;
    o[t] = sh*(1.f/64.f); o[64+t] = sw*(1.f/64.f);
}

// ah/aw sigmoid projections merged: blockIdx.y = 0 (h) / 1 (w)
__global__ void ca_proj_k(const float* __restrict__ wh, const float* __restrict__ bh,
                          const float* __restrict__ ww, const float* __restrict__ bw)
{
    int hw = blockIdx.y, b = blockIdx.z;
    int idx = blockIdx.x*256 + threadIdx.x;       // 16384 per (b,hw)
    int c = idx >> 6, pos = idx & 63;
    const float* W  = hw ? ww : wh;
    const float* Bi = hw ? bw : bh;
    const float* y  = g_yca + (long)b*MIPC*128 + (hw ? 64 : 0) + pos;
    float s = Bi[c];
    #pragma unroll
    for (int i = 0; i < MIPC; i++) s += W[c*MIPC + i] * y[i*128];
    float o = 1.f / (1.f + __expf(-s));
    float* dst = hw ? g_aw : g_ah;
    dst[((long)b*CH + c)*64 + pos] = o;
}

__global__ void ca_apply_k(const float* __restrict__ x, float* __restrict__ r)
{
    long i = blockIdx.x*256L + threadIdx.x;
    if (i >= (long)BATCH*CN) return;
    int c = (int)(i & 255); long t = i >> 8;
    int pix = (int)(t & 4095); int b = (int)(t >> 12);
    long bc = (long)b*CH + c;
    int y = pix >> 6, xx = pix & 63;
    r[i] = x[(long)b*CN + (long)c*NPIX + pix] * g_aw[bc*64+xx] * g_ah[bc*64+y];
}

// ===================== separable maxpool (NHWC, 5-wide) ===============
__global__ void mp_h_k(const float* __restrict__ src, float* __restrict__ tmp)
{
    long i = blockIdx.x*256L + threadIdx.x;
    if (i >= (long)BATCH*CN) return;
    int c = (int)(i & 255); long t = i >> 8;
    int pix = (int)(t & 4095); int b = (int)(t >> 12);
    int y = pix >> 6, x = pix & 63;
    const float* s = src + (long)b*NPIX*1024;
    float m = -3.4e38f;
    #pragma unroll
    for (int d = -2; d <= 2; d++) {
        int xx = x + d;
        if ((unsigned)xx < 64u) m = fmaxf(m, s[(long)((y<<6)+xx)*1024 + c]);
    }
    tmp[(long)b*CN + (long)pix*256 + c] = m;
}
__global__ void mp_v_k(const float* __restrict__ tmp, float* __restrict__ dst)
{
    long i = blockIdx.x*256L + threadIdx.x;
    if (i >= (long)BATCH*CN) return;
    int c = (int)(i & 255); long t = i >> 8;
    int pix = (int)(t & 4095); int b = (int)(t >> 12);
    int y = pix >> 6, x = pix & 63;
    const float* s = tmp + (long)b*CN;
    float m = -3.4e38f;
    #pragma unroll
    for (int d = -2; d <= 2; d++) {
        int yy = y + d;
        if ((unsigned)yy < 64u) m = fmaxf(m, s[(long)((yy<<6)+x)*256 + c]);
    }
    dst[(long)b*NPIX*1024 + (long)pix*1024 + c] = m;
}

// ===================== PAM softmax (rows of 4096) =====================
__global__ void softmax_row_k(float* __restrict__ a)
{
    float* p = a + (long)blockIdx.x * 4096;
    int t = threadIdx.x;
    __shared__ float red[256];
    float v[16];
    #pragma unroll
    for (int i = 0; i < 16; i++) v[i] = p[t + i*256];
    float mx = v[0];
    #pragma unroll
    for (int i = 1; i < 16; i++) mx = fmaxf(mx, v[i]);
    red[t] = mx; __syncthreads();
    for (int s = 128; s > 0; s >>= 1) { if (t < s) red[t] = fmaxf(red[t], red[t+s]); __syncthreads(); }
    mx = red[0]; __syncthreads();
    float sum = 0.f;
    #pragma unroll
    for (int i = 0; i < 16; i++) { v[i] = __expf(v[i] - mx); sum += v[i]; }
    red[t] = sum; __syncthreads();
    for (int s = 128; s > 0; s >>= 1) { if (t < s) red[t] += red[t+s]; __syncthreads(); }
    float inv = 1.f / red[0];
    #pragma unroll
    for (int i = 0; i < 16; i++) p[t + i*256] = v[i] * inv;
}

// ===================== CAM: split-K reduce + softmax ===================
__global__ void e_reduce_k(const float* __restrict__ ep, float* __restrict__ e)
{
    int i = blockIdx.x*256 + threadIdx.x;     // < BATCH*65536
    int b = i >> 16, r = i & 65535;
    float s = 0.f;
    #pragma unroll
    for (int k = 0; k < ESPLIT; k++)
        s += ep[((long)(b*ESPLIT + k) << 16) + r];
    e[i] = s;
}

__global__ void cam_softmax_k(const float* __restrict__ e, float* __restrict__ ac)
{
    long row = blockIdx.x;
    const float* p = e + row*256;
    int t = threadIdx.x;
    __shared__ float sm[256];
    float v = p[t];
    sm[t] = v; __syncthreads();
    for (int s = 128; s > 0; s >>= 1) { if (t < s) sm[t] = fmaxf(sm[t], sm[t+s]); __syncthreads(); }
    float rowmax = sm[0]; __syncthreads();
    float z = rowmax - v;
    sm[t] = z; __syncthreads();
    for (int s = 128; s > 0; s >>= 1) { if (t < s) sm[t] = fmaxf(sm[t], sm[t+s]); __syncthreads(); }
    float zm = sm[0]; __syncthreads();
    float pe = __expf(z - zm);
    sm[t] = pe; __syncthreads();
    for (int s = 128; s > 0; s >>= 1) { if (t < s) sm[t] += sm[t+s]; __syncthreads(); }
    ac[row*256 + t] = pe / sm[0];
}

// ===================== tiled transpose NHWC -> NCHW ====================
__global__ void transpose_k(const float* __restrict__ src, float* __restrict__ dst)
{
    __shared__ float s[32][33];
    int b = blockIdx.z;
    int p0 = blockIdx.x*32, c0 = blockIdx.y*32;
    int tx = threadIdx.x, ty = threadIdx.y;  // 32 x 8
    const float* S = src + (long)b*CN;
    float* D = dst + (long)b*CN;
    #pragma unroll
    for (int j = 0; j < 32; j += 8)
        s[ty+j][tx] = S[(long)(p0+ty+j)*256 + c0+tx];
    __syncthreads();
    #pragma unroll
    for (int j = 0; j < 32; j += 8)
        D[(long)(c0+ty+j)*4096 + p0+tx] = s[tx][ty+j];
}

// ======================================================================
extern "C" void kernel_launch(void* const* d_in, const int* in_sizes, int n_in,
                              void* d_out, int out_size)
{
    const float* x     = (const float*)d_in[0];
    const float* ca_w1 = (const float*)d_in[1];
    const float* ca_b1 = (const float*)d_in[2];
    const float* ca_bn = (const float*)d_in[3];
    const float* ca_wh = (const float*)d_in[4];
    const float* ca_bh = (const float*)d_in[5];
    const float* ca_ww = (const float*)d_in[6];
    const float* ca_bw = (const float*)d_in[7];
    const float* s1_w  = (const float*)d_in[8];  const float* s1_bn = (const float*)d_in[9];
    const float* s2_w  = (const float*)d_in[10]; const float* s2_bn = (const float*)d_in[11];
    const float* s3_w  = (const float*)d_in[12]; const float* s3_bn = (const float*)d_in[13];
    const float* s4_w  = (const float*)d_in[14]; const float* s4_bn = (const float*)d_in[15];
    const float* s5_w  = (const float*)d_in[16]; const float* s5_bn = (const float*)d_in[17];
    const float* s6_w  = (const float*)d_in[18]; const float* s6_bn = (const float*)d_in[19];
    const float* s7_w  = (const float*)d_in[20]; const float* s7_bn = (const float*)d_in[21];
    const float* pq_w  = (const float*)d_in[22]; const float* pq_b  = (const float*)d_in[23];
    const float* pk_w  = (const float*)d_in[24]; const float* pk_b  = (const float*)d_in[25];
    const float* pv_w  = (const float*)d_in[26]; const float* pv_b  = (const float*)d_in[27];
    const float* gpa   = (const float*)d_in[28];
    const float* gca   = (const float*)d_in[29];

    float *pool,*yca,*r,*t1,*t2,*cat,*mp,*yc,*res,*resT,*qk,*vb,*attn,*pam,*e,*epart,*ac;
    float *w1f,*b1f,*ws1,*bs1,*ws2,*bs2,*ws3,*bs3,*ws4,*bs4,*ws5,*bs5,*ws6,*bs6,*ws7,*bs7,*wqk,*bqk;
    cudaGetSymbolAddress((void**)&pool, g_pool);  cudaGetSymbolAddress((void**)&yca, g_yca);
    cudaGetSymbolAddress((void**)&r, g_r);        cudaGetSymbolAddress((void**)&t1, g_t1);
    cudaGetSymbolAddress((void**)&t2, g_t2);      cudaGetSymbolAddress((void**)&cat, g_cat);
    cudaGetSymbolAddress((void**)&mp, g_mp);      cudaGetSymbolAddress((void**)&yc, g_yc);
    cudaGetSymbolAddress((void**)&res, g_res);    cudaGetSymbolAddress((void**)&resT, g_resT);
    cudaGetSymbolAddress((void**)&qk, g_qk);      cudaGetSymbolAddress((void**)&vb, g_v);
    cudaGetSymbolAddress((void**)&attn, g_attn);  cudaGetSymbolAddress((void**)&pam, g_pam);
    cudaGetSymbolAddress((void**)&e, g_e);        cudaGetSymbolAddress((void**)&epart, g_epart);
    cudaGetSymbolAddress((void**)&ac, g_ac);
    cudaGetSymbolAddress((void**)&w1f, g_w1f);    cudaGetSymbolAddress((void**)&b1f, g_b1f);
    cudaGetSymbolAddress((void**)&ws1, g_ws1);    cudaGetSymbolAddress((void**)&bs1, g_bs1);
    cudaGetSymbolAddress((void**)&ws2, g_ws2);    cudaGetSymbolAddress((void**)&bs2, g_bs2);
    cudaGetSymbolAddress((void**)&ws3, g_ws3);    cudaGetSymbolAddress((void**)&bs3, g_bs3);
    cudaGetSymbolAddress((void**)&ws4, g_ws4);    cudaGetSymbolAddress((void**)&bs4, g_bs4);
    cudaGetSymbolAddress((void**)&ws5, g_ws5);    cudaGetSymbolAddress((void**)&bs5, g_bs5);
    cudaGetSymbolAddress((void**)&ws6, g_ws6);    cudaGetSymbolAddress((void**)&bs6, g_bs6);
    cudaGetSymbolAddress((void**)&ws7, g_ws7);    cudaGetSymbolAddress((void**)&bs7, g_bs7);
    cudaGetSymbolAddress((void**)&wqk, g_wqk);    cudaGetSymbolAddress((void**)&bqk, g_bqk);

    const int SMEMSZ = SMEM_FLOATS * 4;
    cudaFuncSetAttribute(mma_gemm<0,false>, cudaFuncAttributeMaxDynamicSharedMemorySize, SMEMSZ);
    cudaFuncSetAttribute(mma_gemm<1,false>, cudaFuncAttributeMaxDynamicSharedMemorySize, SMEMSZ);
    cudaFuncSetAttribute(mma_gemm<1,true>,  cudaFuncAttributeMaxDynamicSharedMemorySize, SMEMSZ);
    cudaFuncSetAttribute(mma_gemm<4,false>, cudaFuncAttributeMaxDynamicSharedMemorySize, SMEMSZ);

    const int EB = (BATCH*CN + 255)/256;

    // ---- 1: merged BN folds + qk concat ----
    FoldArgs fa;
    fa.w[0]=ca_w1; fa.bn[0]=ca_bn; fa.bin[0]=ca_b1; fa.wf[0]=w1f; fa.bf[0]=b1f; fa.O[0]=MIPC; fa.Ke[0]=256;  fa.ro[0]=0;
    fa.w[1]=s1_w;  fa.bn[1]=s1_bn; fa.bin[1]=nullptr; fa.wf[1]=ws1; fa.bf[1]=bs1; fa.O[1]=CH; fa.Ke[1]=256;  fa.ro[1]=0;
    fa.w[2]=s2_w;  fa.bn[2]=s2_bn; fa.bin[2]=nullptr; fa.wf[2]=ws2; fa.bf[2]=bs2; fa.O[2]=CH; fa.Ke[2]=256;  fa.ro[2]=0;
    fa.w[3]=s3_w;  fa.bn[3]=s3_bn; fa.bin[3]=nullptr; fa.wf[3]=ws3; fa.bf[3]=bs3; fa.O[3]=CH; fa.Ke[3]=2304; fa.ro[3]=1;
    fa.w[4]=s4_w;  fa.bn[4]=s4_bn; fa.bin[4]=nullptr; fa.wf[4]=ws4; fa.bf[4]=bs4; fa.O[4]=CH; fa.Ke[4]=256;  fa.ro[4]=0;
    fa.w[5]=s5_w;  fa.bn[5]=s5_bn; fa.bin[5]=nullptr; fa.wf[5]=ws5; fa.bf[5]=bs5; fa.O[5]=CH; fa.Ke[5]=1024; fa.ro[5]=0;
    fa.w[6]=s6_w;  fa.bn[6]=s6_bn; fa.bin[6]=nullptr; fa.wf[6]=ws6; fa.bf[6]=bs6; fa.O[6]=CH; fa.Ke[6]=2304; fa.ro[6]=1;
    fa.w[7]=s7_w;  fa.bn[7]=s7_bn; fa.bin[7]=nullptr; fa.wf[7]=ws7; fa.bf[7]=bs7; fa.O[7]=CH; fa.Ke[7]=512;  fa.ro[7]=0;
    fa.pq_w=pq_w; fa.pq_b=pq_b; fa.pk_w=pk_w; fa.pk_b=pk_b; fa.qkw=wqk; fa.qkb=bqk;
    fold_all_k<<<dim3(256,9),256>>>(fa);

    // ---- 2-5: CoordAtt ----
    ca_pool_k<<<dim3(CH,BATCH),64>>>(x, pool);
    gemm_small<2><<<dim3(2,1,BATCH),256>>>(w1f, pool, b1f, yca,
        MIPC,128,CH, 128, 0, (long)CH*128, (long)MIPC*128);
    ca_proj_k<<<dim3(64,2,BATCH),256>>>(ca_wh, ca_bh, ca_ww, ca_bw);
    ca_apply_k<<<EB,256>>>(x, r);

    // ---- 6+: SPPCSPC (launch #6 = s1 GEMM, in ncu window) ----
    mma_gemm<1,false><<<dim3(2,32,BATCH),256,SMEMSZ>>>(r, ws1, bs1, t1,
        256,256,256,256, 256,256,0, (long)CN,0,(long)CN);
    mma_gemm<1,true ><<<dim3(2,32,BATCH),256,SMEMSZ>>>(t1, ws3, bs3, t2,
        2304,256,2304,256, 256,256,0, (long)CN,0,(long)CN);
    mma_gemm<1,false><<<dim3(2,32,BATCH),256,SMEMSZ>>>(t2, ws4, bs4, cat,
        256,256,256,1024, 256,256,0, (long)CN,0,(long)NPIX*1024);
    mp_h_k<<<EB,256>>>(cat,       mp); mp_v_k<<<EB,256>>>(mp, cat+256);
    mp_h_k<<<EB,256>>>(cat+256,   mp); mp_v_k<<<EB,256>>>(mp, cat+512);
    mp_h_k<<<EB,256>>>(cat+512,   mp); mp_v_k<<<EB,256>>>(mp, cat+768);
    mma_gemm<1,false><<<dim3(2,32,BATCH),256,SMEMSZ>>>(cat, ws5, bs5, t1,
        1024,1024,1024,256, 256,256,0, (long)NPIX*1024,0,(long)CN);
    mma_gemm<1,true ><<<dim3(2,32,BATCH),256,SMEMSZ>>>(t1, ws6, bs6, yc,
        2304,256,2304,512, 256,256,0, (long)CN,0,(long)NPIX*512);
    mma_gemm<1,false><<<dim3(2,32,BATCH),256,SMEMSZ>>>(r, ws2, bs2, yc+256,
        256,256,256,512, 256,256,0, (long)CN,0,(long)NPIX*512);
    mma_gemm<1,false><<<dim3(2,32,BATCH),256,SMEMSZ>>>(yc, ws7, bs7, res,
        512,512,512,256, 256,256,0, (long)NPIX*512,0,(long)CN);

    // ---- PAM ----
    mma_gemm<0,false><<<dim3(1,32,BATCH),256,SMEMSZ>>>(res, wqk, bqk, qk,
        256,256,256,64, 64,64,0, (long)CN,0,(long)NPIX*64);
    mma_gemm<0,false><<<dim3(32,2,BATCH),256,SMEMSZ>>>(pv_w, res, pv_b, vb,
        256,256,256,NPIX, NPIX,NPIX,1, 0,(long)CN,(long)CN);
    mma_gemm<0,false><<<dim3(32,32,BATCH),256,SMEMSZ>>>(qk, qk+32, nullptr, attn,
        CQD,64,64,NPIX, NPIX,NPIX,0, (long)NPIX*64,(long)NPIX*64,(long)NPIX*NPIX);
    softmax_row_k<<<BATCH*NPIX,256>>>(attn);
    mma_gemm<0,false><<<dim3(32,2,BATCH),256,SMEMSZ>>>(vb, attn, nullptr, pam,
        NPIX,NPIX,NPIX,NPIX, NPIX,NPIX,0, (long)CN,(long)NPIX*NPIX,(long)CN);

    // ---- CAM (split-K e) ----
    transpose_k<<<dim3(128,8,BATCH),dim3(32,8)>>>(res, resT);
    mma_gemm<0,false><<<dim3(2,2,BATCH*ESPLIT),256,SMEMSZ>>>(resT, resT, nullptr, epart,
        NPIX/ESPLIT,NPIX,NPIX,256, 256,256,0, (long)CN,(long)CN,(long)CH*CH, ESPLIT);
    e_reduce_k<<<(BATCH*CH*CH+255)/256,256>>>(epart, e);
    cam_softmax_k<<<BATCH*CH,256>>>(e, ac);
    // cam GEMM + fused final combine -> d_out
    mma_gemm<4,false><<<dim3(32,2,BATCH),256,SMEMSZ>>>(ac, res, nullptr, (float*)d_out,
        256,256,256,NPIX, NPIX,NPIX,0, (long)CH*CH,(long)CN,(long)CN,
        1, resT, pam, gpa, gca);
}

// round 5
// speedup vs baseline: 4.3748x; 1.2657x over previous
#include <cuda_runtime.h>
#include <cuda_fp16.h>
#include <cstdint>

// Problem constants
#define BATCH 2
#define CH    256
#define NPIX  4096
#define MIPC  8
#define CQD   32
#define CN    (CH*NPIX)
#define ESPLIT 8

// ===================== static scratch ==================================
__device__ float g_pool[BATCH*CH*128];
__device__ float g_yca [BATCH*MIPC*128];
__device__ float g_ah  [BATCH*CH*64];
__device__ float g_aw  [BATCH*CH*64];
__device__ float g_r   [BATCH*CN];            // NHWC [b][pix][256]
__device__ float g_t1  [BATCH*CN];
__device__ float g_t2  [BATCH*CN];
__device__ float g_cat [(long)BATCH*NPIX*1024];  // NHWC [b][pix][1024]
__device__ float g_mp  [BATCH*CN];
__device__ float g_yc  [(long)BATCH*NPIX*512];   // NHWC [b][pix][512]
__device__ float g_res [BATCH*CN];            // NHWC
__device__ float g_resT[BATCH*CN];            // NCHW
__device__ float g_qk  [BATCH*NPIX*64];       // [b][pix][64]: q|k
__device__ float g_v   [BATCH*CN];            // NCHW
__device__ float g_attn[(long)BATCH*NPIX*NPIX];
__device__ float g_pam [BATCH*CN];            // NCHW
__device__ float g_e   [BATCH*CH*CH];
__device__ float g_epart[BATCH*ESPLIT*CH*CH];
__device__ float g_ac  [BATCH*CH*CH];
__device__ float g_w1f[MIPC*CH];   __device__ float g_b1f[MIPC];
__device__ float g_ws1[CH*CH];     __device__ float g_bs1[CH];
__device__ float g_ws2[CH*CH];     __device__ float g_bs2[CH];
__device__ float g_ws3[CH*2304];   __device__ float g_bs3[CH];
__device__ float g_ws4[CH*CH];     __device__ float g_bs4[CH];
__device__ float g_ws5[CH*1024];   __device__ float g_bs5[CH];
__device__ float g_ws6[CH*2304];   __device__ float g_bs6[CH];
__device__ float g_ws7[CH*512];    __device__ float g_bs7[CH];
__device__ float g_wqk[64*CH];     __device__ float g_bqk[64];

// ===================== merged BN fold (all jobs, 1 launch) =============
struct FoldArgs {
    const float* w[8]; const float* bn[8]; const float* bin[8];
    float* wf[8]; float* bf[8];
    int O[8]; int Ke[8]; int ro[8];
    const float *pq_w, *pq_b, *pk_w, *pk_b;
    float *qkw, *qkb;
};

__global__ void fold_all_k(FoldArgs a)
{
    int j = blockIdx.y, o = blockIdx.x;
    if (j == 8) {  // qk weight/bias concat
        if (o >= 64) return;
        const float* src = (o < 32) ? (a.pq_w + (long)o*256)
                                    : (a.pk_w + (long)(o-32)*256);
        for (int k = threadIdx.x; k < 256; k += blockDim.x)
            a.qkw[(long)o*256 + k] = src[k];
        if (threadIdx.x == 0)
            a.qkb[o] = (o < 32) ? a.pq_b[o] : a.pk_b[o-32];
        return;
    }
    int O = a.O[j];
    if (o >= O) return;
    const float* bn = a.bn[j];
    float g  = bn[o], be = bn[O+o], mn = bn[2*O+o], vr = bn[3*O+o];
    float s = g * rsqrtf(vr + 1e-5f);
    int Ke = a.Ke[j];
    const float* w = a.w[j];
    float* wf = a.wf[j];
    if (a.ro[j]) {
        for (int k = threadIdx.x; k < Ke; k += blockDim.x) {
            int t = k >> 8, ci = k & 255;
            wf[(long)o*Ke + k] = w[((long)o*256 + ci)*9 + t] * s;
        }
    } else {
        for (int k = threadIdx.x; k < Ke; k += blockDim.x)
            wf[(long)o*Ke + k] = w[(long)o*Ke + k] * s;
    }
    if (threadIdx.x == 0)
        a.bf[j][o] = (a.bin[j] ? a.bin[j][o] : 0.f) * s + be - mn * s;
}

// ===================== fp16 mma.sync GEMM ==============================
__device__ __forceinline__ uint2 cvt4h(float4 v) {
    __half2 lo = __floats2half2_rn(v.x, v.y);
    __half2 hi = __floats2half2_rn(v.z, v.w);
    uint2 o;
    o.x = *(uint32_t*)&lo;
    o.y = *(uint32_t*)&hi;
    return o;
}
__device__ __forceinline__ void mma_f16(float c[4], const uint32_t a[4],
                                        const uint32_t b[2]) {
    asm volatile(
        "mma.sync.aligned.m16n8k16.row.col.f32.f16.f16.f32 "
        "{%0,%1,%2,%3}, {%4,%5,%6,%7}, {%8,%9}, {%0,%1,%2,%3};"
        : "+f"(c[0]), "+f"(c[1]), "+f"(c[2]), "+f"(c[3])
        : "r"(a[0]), "r"(a[1]), "r"(a[2]), "r"(a[3]), "r"(b[0]), "r"(b[1]));
}

// SMEM rows: 32 halves data + 8 halves pad = 20 words. Conflict-free frag LDS.
#define ROWW 20
#define STG_STRIDE (128*ROWW)          // 2560 words per stage per operand
#define B_BASE (2*STG_STRIDE)
#define SMEM_WORDS (4*STG_STRIDE)      // 10240 words = 40 KB

// D[m0..+127][n0..+127] = act( sum_k A[m][k]*B[n][k] + bias )
// ACT: 0 none, 1 SiLU, 4 final-combine (3*f1 + gam1*f2 + gam2*acc)
template<int ACT, bool CONV3>
__global__ __launch_bounds__(256) void mma_gemm(
    const float* __restrict__ A, const float* __restrict__ B,
    const float* __restrict__ bias, float* __restrict__ C,
    int K, int lda, int ldb, int ldc, int Bn, int ncols, int bias_on_m,
    long sA_, long sB_, long sC_,
    int nsplit = 1,
    const float* __restrict__ f1 = nullptr, const float* __restrict__ f2 = nullptr,
    const float* __restrict__ gam1 = nullptr, const float* __restrict__ gam2 = nullptr)
{
    extern __shared__ uint32_t smu[];

    int bz = blockIdx.z;
    int batch = bz, slice = 0;
    if (nsplit > 1) { batch = bz / nsplit; slice = bz - batch * nsplit; }
    A += batch * sA_ + (long)slice * K;
    B += batch * sB_ + (long)slice * K;
    C += (long)bz * sC_;
    if (ACT == 4) { f1 += (long)batch * CN; f2 += (long)batch * CN; }
    float gg1 = 0.f, gg2 = 0.f;
    if (ACT == 4) { gg1 = gam1[0]; gg2 = gam2[0]; }

    int m0 = blockIdx.y * 128, n0 = blockIdx.x * 128;
    int tid = threadIdx.x;
    int lane = tid & 31, w = tid >> 5;
    int wm = w >> 1, wn = w & 1;           // 4 x 2 warp grid; warp tile 32x64
    int g = lane >> 2, t = lane & 3;

    float acc[2][8][4] = {};
    uint2 bufA[4], bufB[4];

    auto ldg = [&](int it) {
        int k0 = it * 32;
        if (!CONV3) {
            #pragma unroll
            for (int i = 0; i < 4; i++) {
                int f = i*256 + tid; int m = f >> 3; int c4 = f & 7;
                bufA[i] = cvt4h(*(const float4*)(A + (long)(m0+m)*lda + k0 + c4*4));
            }
        } else {
            int tap = k0 >> 8, ci0 = k0 & 255;
            int dy = tap/3 - 1, dx = tap%3 - 1;
            #pragma unroll
            for (int i = 0; i < 4; i++) {
                int f = i*256 + tid; int m = f >> 3; int c4 = f & 7;
                int pix = m0 + m;
                int y = (pix >> 6) + dy, x = (pix & 63) + dx;
                float4 v = make_float4(0.f,0.f,0.f,0.f);
                if ((unsigned)y < 64u && (unsigned)x < 64u)
                    v = *(const float4*)(A + (long)((y<<6)+x)*lda + ci0 + c4*4);
                bufA[i] = cvt4h(v);
            }
        }
        #pragma unroll
        for (int i = 0; i < 4; i++) {
            int f = i*256 + tid; int n = f >> 3; int c4 = f & 7;
            float4 v = make_float4(0.f,0.f,0.f,0.f);
            if (n0 + n < Bn)
                v = *(const float4*)(B + (long)(n0+n)*ldb + k0 + c4*4);
            bufB[i] = cvt4h(v);
        }
    };
    auto sts = [&](int s) {
        #pragma unroll
        for (int i = 0; i < 4; i++) {
            int f = i*256 + tid; int m = f >> 3; int c4 = f & 7;
            int off = s*STG_STRIDE + m*ROWW + c4*2;
            *(uint2*)(smu + off) = bufA[i];
            *(uint2*)(smu + B_BASE + off) = bufB[i];
        }
    };
    auto compute = [&](int s) {
        #pragma unroll
        for (int ks = 0; ks < 2; ks++) {     // two k16 steps per 32-K tile
            uint32_t af[2][4], bf[8][2];
            #pragma unroll
            for (int mt = 0; mt < 2; mt++) {
                int base = s*STG_STRIDE + (wm*32 + mt*16 + g)*ROWW + ks*8;
                af[mt][0] = smu[base + t];
                af[mt][1] = smu[base + 8*ROWW + t];
                af[mt][2] = smu[base + t + 4];
                af[mt][3] = smu[base + 8*ROWW + t + 4];
            }
            #pragma unroll
            for (int nt = 0; nt < 8; nt++) {
                int base = B_BASE + s*STG_STRIDE + (wn*64 + nt*8 + g)*ROWW + ks*8;
                bf[nt][0] = smu[base + t];
                bf[nt][1] = smu[base + t + 4];
            }
            #pragma unroll
            for (int mt = 0; mt < 2; mt++)
                #pragma unroll
                for (int nt = 0; nt < 8; nt++)
                    mma_f16(acc[mt][nt], af[mt], bf[nt]);
        }
    };

    int T = K >> 5;
    ldg(0);
    sts(0);
    __syncthreads();
    for (int it = 0; it < T; it++) {
        if (it + 1 < T) ldg(it + 1);
        compute(it & 1);
        if (it + 1 < T) {
            __syncthreads();
            sts((it + 1) & 1);
            __syncthreads();
        }
    }

    // epilogue
    int valid = ncols - n0; if (valid > 128) valid = 128;
    #pragma unroll
    for (int mt = 0; mt < 2; mt++) {
        #pragma unroll
        for (int half = 0; half < 2; half++) {
            int m = m0 + wm*32 + mt*16 + g + half*8;
            float bm = (bias && bias_on_m) ? bias[m] : 0.f;
            long base = (long)m*ldc + n0;
            float* Crow = C + base;
            #pragma unroll
            for (int nt = 0; nt < 8; nt++) {
                int nl = wn*64 + nt*8 + 2*t;
                if (nl >= valid) continue;
                float v0 = acc[mt][nt][half*2 + 0] + bm;
                float v1 = acc[mt][nt][half*2 + 1] + bm;
                if (bias && !bias_on_m) { v0 += bias[n0+nl]; v1 += bias[n0+nl+1]; }
                if (ACT == 1) {
                    v0 = v0 / (1.f + __expf(-v0));
                    v1 = v1 / (1.f + __expf(-v1));
                } else if (ACT == 4) {
                    float2 r1 = *(const float2*)(f1 + base + nl);
                    float2 r2 = *(const float2*)(f2 + base + nl);
                    v0 = 3.f*r1.x + gg1*r2.x + gg2*v0;
                    v1 = 3.f*r1.y + gg1*r2.y + gg2*v1;
                }
                *(float2*)(Crow + nl) = make_float2(v0, v1);
            }
        }
    }
}

// ===================== small FMA GEMM (CoordAtt yca only) =============
template<int ACT>
__global__ __launch_bounds__(256) void gemm_small(
    const float* __restrict__ A, const float* __restrict__ B,
    const float* __restrict__ bias, float* __restrict__ C,
    int M, int N, int K, int ldb, long sA, long sB, long sC)
{
    int b = blockIdx.z;
    A += (long)b*sA; B += (long)b*sB; C += (long)b*sC;
    int m0 = blockIdx.y*64, n0 = blockIdx.x*64;
    __shared__ float As[16][64], Bs[16][65];
    int tid = threadIdx.x, tx = tid & 15, ty = tid >> 4;
    float acc[4][4] = {};
    for (int k0 = 0; k0 < K; k0 += 16) {
        int i = tid >> 2, jb = (tid & 3)*4, mI = m0 + i;
        #pragma unroll
        for (int j = 0; j < 4; j++) {
            int k = k0 + jb + j;
            As[jb+j][i] = (mI < M && k < K) ? A[(long)mI*K + k] : 0.f;
        }
        int jr = tid >> 4, nb = (tid & 15)*4, k = k0 + jr;
        #pragma unroll
        for (int n = 0; n < 4; n++) {
            int nn = n0 + nb + n;
            Bs[jr][nb+n] = (k < K && nn < N) ? B[(long)k*ldb + nn] : 0.f;
        }
        __syncthreads();
        #pragma unroll
        for (int j = 0; j < 16; j++) {
            float a[4], bb[4];
            #pragma unroll
            for (int i2 = 0; i2 < 4; i2++) a[i2]  = As[j][ty*4+i2];
            #pragma unroll
            for (int i2 = 0; i2 < 4; i2++) bb[i2] = Bs[j][tx*4+i2];
            #pragma unroll
            for (int i2 = 0; i2 < 4; i2++)
                #pragma unroll
                for (int jj = 0; jj < 4; jj++) acc[i2][jj] += a[i2]*bb[jj];
        }
        __syncthreads();
    }
    #pragma unroll
    for (int i = 0; i < 4; i++) {
        int mI = m0 + ty*4 + i;
        if (mI >= M) continue;
        float bv = bias ? bias[mI] : 0.f;
        #pragma unroll
        for (int jj = 0; jj < 4; jj++) {
            int n = n0 + tx*4 + jj;
            if (n >= N) continue;
            float v = acc[i][jj] + bv;
            if (ACT == 2) { float tq = fminf(fmaxf(v+3.f,0.f),6.f); v = v*tq*(1.f/6.f); }
            C[(long)mI*N + n] = v;
        }
    }
}

// ===================== CoordAtt glue ==================================
__global__ void ca_pool_k(const float* __restrict__ x, float* __restrict__ pool)
{
    int c = blockIdx.x, b = blockIdx.y, t = threadIdx.x;
    const float* p = x + ((long)b*CH + c)*NPIX;
    float sh = 0.f, sw = 0.f;
    for (int i = 0; i < 64; i++) sh += p[t*64 + i];
    for (int i = 0; i < 64; i++) sw += p[i*64 + t];
    float* o = pool + ((long)b*CH + c)*128;
    o[t] = sh*(1.f/64.f); o[64+t] = sw*(1.f/64.f);
}

__global__ void ca_proj_k(const float* __restrict__ wh, const float* __restrict__ bh,
                          const float* __restrict__ ww, const float* __restrict__ bw)
{
    int hw = blockIdx.y, b = blockIdx.z;
    int idx = blockIdx.x*256 + threadIdx.x;
    int c = idx >> 6, pos = idx & 63;
    const float* W  = hw ? ww : wh;
    const float* Bi = hw ? bw : bh;
    const float* y  = g_yca + (long)b*MIPC*128 + (hw ? 64 : 0) + pos;
    float s = Bi[c];
    #pragma unroll
    for (int i = 0; i < MIPC; i++) s += W[c*MIPC + i] * y[i*128];
    float o = 1.f / (1.f + __expf(-s));
    float* dst = hw ? g_aw : g_ah;
    dst[((long)b*CH + c)*64 + pos] = o;
}

__global__ void ca_apply_k(const float* __restrict__ x, float* __restrict__ r)
{
    long i = blockIdx.x*256L + threadIdx.x;
    if (i >= (long)BATCH*CN) return;
    int c = (int)(i & 255); long t = i >> 8;
    int pix = (int)(t & 4095); int b = (int)(t >> 12);
    long bc = (long)b*CH + c;
    int y = pix >> 6, xx = pix & 63;
    r[i] = x[(long)b*CN + (long)c*NPIX + pix] * g_aw[bc*64+xx] * g_ah[bc*64+y];
}

// ===================== separable maxpool (NHWC, 5-wide) ===============
__global__ void mp_h_k(const float* __restrict__ src, float* __restrict__ tmp)
{
    long i = blockIdx.x*256L + threadIdx.x;
    if (i >= (long)BATCH*CN) return;
    int c = (int)(i & 255); long t = i >> 8;
    int pix = (int)(t & 4095); int b = (int)(t >> 12);
    int y = pix >> 6, x = pix & 63;
    const float* s = src + (long)b*NPIX*1024;
    float m = -3.4e38f;
    #pragma unroll
    for (int d = -2; d <= 2; d++) {
        int xx = x + d;
        if ((unsigned)xx < 64u) m = fmaxf(m, s[(long)((y<<6)+xx)*1024 + c]);
    }
    tmp[(long)b*CN + (long)pix*256 + c] = m;
}
__global__ void mp_v_k(const float* __restrict__ tmp, float* __restrict__ dst)
{
    long i = blockIdx.x*256L + threadIdx.x;
    if (i >= (long)BATCH*CN) return;
    int c = (int)(i & 255); long t = i >> 8;
    int pix = (int)(t & 4095); int b = (int)(t >> 12);
    int y = pix >> 6, x = pix & 63;
    const float* s = tmp + (long)b*CN;
    float m = -3.4e38f;
    #pragma unroll
    for (int d = -2; d <= 2; d++) {
        int yy = y + d;
        if ((unsigned)yy < 64u) m = fmaxf(m, s[(long)((yy<<6)+x)*256 + c]);
    }
    dst[(long)b*NPIX*1024 + (long)pix*1024 + c] = m;
}

// ===================== PAM softmax (rows of 4096) =====================
__global__ void softmax_row_k(float* __restrict__ a)
{
    float* p = a + (long)blockIdx.x * 4096;
    int t = threadIdx.x;
    __shared__ float red[256];
    float v[16];
    #pragma unroll
    for (int i = 0; i < 16; i++) v[i] = p[t + i*256];
    float mx = v[0];
    #pragma unroll
    for (int i = 1; i < 16; i++) mx = fmaxf(mx, v[i]);
    red[t] = mx; __syncthreads();
    for (int s = 128; s > 0; s >>= 1) { if (t < s) red[t] = fmaxf(red[t], red[t+s]); __syncthreads(); }
    mx = red[0]; __syncthreads();
    float sum = 0.f;
    #pragma unroll
    for (int i = 0; i < 16; i++) { v[i] = __expf(v[i] - mx); sum += v[i]; }
    red[t] = sum; __syncthreads();
    for (int s = 128; s > 0; s >>= 1) { if (t < s) red[t] += red[t+s]; __syncthreads(); }
    float inv = 1.f / red[0];
    #pragma unroll
    for (int i = 0; i < 16; i++) p[t + i*256] = v[i] * inv;
}

// ===================== CAM: split-K reduce + softmax ===================
__global__ void e_reduce_k(const float* __restrict__ ep, float* __restrict__ e)
{
    int i = blockIdx.x*256 + threadIdx.x;
    int b = i >> 16, r = i & 65535;
    float s = 0.f;
    #pragma unroll
    for (int k = 0; k < ESPLIT; k++)
        s += ep[((long)(b*ESPLIT + k) << 16) + r];
    e[i] = s;
}

__global__ void cam_softmax_k(const float* __restrict__ e, float* __restrict__ ac)
{
    long row = blockIdx.x;
    const float* p = e + row*256;
    int t = threadIdx.x;
    __shared__ float sm[256];
    float v = p[t];
    sm[t] = v; __syncthreads();
    for (int s = 128; s > 0; s >>= 1) { if (t < s) sm[t] = fmaxf(sm[t], sm[t+s]); __syncthreads(); }
    float rowmax = sm[0]; __syncthreads();
    float z = rowmax - v;
    sm[t] = z; __syncthreads();
    for (int s = 128; s > 0; s >>= 1) { if (t < s) sm[t] = fmaxf(sm[t], sm[t+s]); __syncthreads(); }
    float zm = sm[0]; __syncthreads();
    float pe = __expf(z - zm);
    sm[t] = pe; __syncthreads();
    for (int s = 128; s > 0; s >>= 1) { if (t < s) sm[t] += sm[t+s]; __syncthreads(); }
    ac[row*256 + t] = pe / sm[0];
}

// ===================== tiled transpose NHWC -> NCHW ====================
__global__ void transpose_k(const float* __restrict__ src, float* __restrict__ dst)
{
    __shared__ float s[32][33];
    int b = blockIdx.z;
    int p0 = blockIdx.x*32, c0 = blockIdx.y*32;
    int tx = threadIdx.x, ty = threadIdx.y;  // 32 x 8
    const float* S = src + (long)b*CN;
    float* D = dst + (long)b*CN;
    #pragma unroll
    for (int j = 0; j < 32; j += 8)
        s[ty+j][tx] = S[(long)(p0+ty+j)*256 + c0+tx];
    __syncthreads();
    #pragma unroll
    for (int j = 0; j < 32; j += 8)
        D[(long)(c0+ty+j)*4096 + p0+tx] = s[tx][ty+j];
}

// ======================================================================
extern "C" void kernel_launch(void* const* d_in, const int* in_sizes, int n_in,
                              void* d_out, int out_size)
{
    const float* x     = (const float*)d_in[0];
    const float* ca_w1 = (const float*)d_in[1];
    const float* ca_b1 = (const float*)d_in[2];
    const float* ca_bn = (const float*)d_in[3];
    const float* ca_wh = (const float*)d_in[4];
    const float* ca_bh = (const float*)d_in[5];
    const float* ca_ww = (const float*)d_in[6];
    const float* ca_bw = (const float*)d_in[7];
    const float* s1_w  = (const float*)d_in[8];  const float* s1_bn = (const float*)d_in[9];
    const float* s2_w  = (const float*)d_in[10]; const float* s2_bn = (const float*)d_in[11];
    const float* s3_w  = (const float*)d_in[12]; const float* s3_bn = (const float*)d_in[13];
    const float* s4_w  = (const float*)d_in[14]; const float* s4_bn = (const float*)d_in[15];
    const float* s5_w  = (const float*)d_in[16]; const float* s5_bn = (const float*)d_in[17];
    const float* s6_w  = (const float*)d_in[18]; const float* s6_bn = (const float*)d_in[19];
    const float* s7_w  = (const float*)d_in[20]; const float* s7_bn = (const float*)d_in[21];
    const float* pq_w  = (const float*)d_in[22]; const float* pq_b  = (const float*)d_in[23];
    const float* pk_w  = (const float*)d_in[24]; const float* pk_b  = (const float*)d_in[25];
    const float* pv_w  = (const float*)d_in[26]; const float* pv_b  = (const float*)d_in[27];
    const float* gpa   = (const float*)d_in[28];
    const float* gca   = (const float*)d_in[29];

    float *pool,*yca,*r,*t1,*t2,*cat,*mp,*yc,*res,*resT,*qk,*vb,*attn,*pam,*e,*epart,*ac;
    float *w1f,*b1f,*ws1,*bs1,*ws2,*bs2,*ws3,*bs3,*ws4,*bs4,*ws5,*bs5,*ws6,*bs6,*ws7,*bs7,*wqk,*bqk;
    cudaGetSymbolAddress((void**)&pool, g_pool);  cudaGetSymbolAddress((void**)&yca, g_yca);
    cudaGetSymbolAddress((void**)&r, g_r);        cudaGetSymbolAddress((void**)&t1, g_t1);
    cudaGetSymbolAddress((void**)&t2, g_t2);      cudaGetSymbolAddress((void**)&cat, g_cat);
    cudaGetSymbolAddress((void**)&mp, g_mp);      cudaGetSymbolAddress((void**)&yc, g_yc);
    cudaGetSymbolAddress((void**)&res, g_res);    cudaGetSymbolAddress((void**)&resT, g_resT);
    cudaGetSymbolAddress((void**)&qk, g_qk);      cudaGetSymbolAddress((void**)&vb, g_v);
    cudaGetSymbolAddress((void**)&attn, g_attn);  cudaGetSymbolAddress((void**)&pam, g_pam);
    cudaGetSymbolAddress((void**)&e, g_e);        cudaGetSymbolAddress((void**)&epart, g_epart);
    cudaGetSymbolAddress((void**)&ac, g_ac);
    cudaGetSymbolAddress((void**)&w1f, g_w1f);    cudaGetSymbolAddress((void**)&b1f, g_b1f);
    cudaGetSymbolAddress((void**)&ws1, g_ws1);    cudaGetSymbolAddress((void**)&bs1, g_bs1);
    cudaGetSymbolAddress((void**)&ws2, g_ws2);    cudaGetSymbolAddress((void**)&bs2, g_bs2);
    cudaGetSymbolAddress((void**)&ws3, g_ws3);    cudaGetSymbolAddress((void**)&bs3, g_bs3);
    cudaGetSymbolAddress((void**)&ws4, g_ws4);    cudaGetSymbolAddress((void**)&bs4, g_bs4);
    cudaGetSymbolAddress((void**)&ws5, g_ws5);    cudaGetSymbolAddress((void**)&bs5, g_bs5);
    cudaGetSymbolAddress((void**)&ws6, g_ws6);    cudaGetSymbolAddress((void**)&bs6, g_bs6);
    cudaGetSymbolAddress((void**)&ws7, g_ws7);    cudaGetSymbolAddress((void**)&bs7, g_bs7);
    cudaGetSymbolAddress((void**)&wqk, g_wqk);    cudaGetSymbolAddress((void**)&bqk, g_bqk);

    const int SMEMSZ = SMEM_WORDS * 4;   // 40960 B
    cudaFuncSetAttribute(mma_gemm<0,false>, cudaFuncAttributeMaxDynamicSharedMemorySize, SMEMSZ);
    cudaFuncSetAttribute(mma_gemm<1,false>, cudaFuncAttributeMaxDynamicSharedMemorySize, SMEMSZ);
    cudaFuncSetAttribute(mma_gemm<1,true>,  cudaFuncAttributeMaxDynamicSharedMemorySize, SMEMSZ);
    cudaFuncSetAttribute(mma_gemm<4,false>, cudaFuncAttributeMaxDynamicSharedMemorySize, SMEMSZ);

    const int EB = (BATCH*CN + 255)/256;

    // ---- merged BN folds + qk concat ----
    FoldArgs fa;
    fa.w[0]=ca_w1; fa.bn[0]=ca_bn; fa.bin[0]=ca_b1; fa.wf[0]=w1f; fa.bf[0]=b1f; fa.O[0]=MIPC; fa.Ke[0]=256;  fa.ro[0]=0;
    fa.w[1]=s1_w;  fa.bn[1]=s1_bn; fa.bin[1]=nullptr; fa.wf[1]=ws1; fa.bf[1]=bs1; fa.O[1]=CH; fa.Ke[1]=256;  fa.ro[1]=0;
    fa.w[2]=s2_w;  fa.bn[2]=s2_bn; fa.bin[2]=nullptr; fa.wf[2]=ws2; fa.bf[2]=bs2; fa.O[2]=CH; fa.Ke[2]=256;  fa.ro[2]=0;
    fa.w[3]=s3_w;  fa.bn[3]=s3_bn; fa.bin[3]=nullptr; fa.wf[3]=ws3; fa.bf[3]=bs3; fa.O[3]=CH; fa.Ke[3]=2304; fa.ro[3]=1;
    fa.w[4]=s4_w;  fa.bn[4]=s4_bn; fa.bin[4]=nullptr; fa.wf[4]=ws4; fa.bf[4]=bs4; fa.O[4]=CH; fa.Ke[4]=256;  fa.ro[4]=0;
    fa.w[5]=s5_w;  fa.bn[5]=s5_bn; fa.bin[5]=nullptr; fa.wf[5]=ws5; fa.bf[5]=bs5; fa.O[5]=CH; fa.Ke[5]=1024; fa.ro[5]=0;
    fa.w[6]=s6_w;  fa.bn[6]=s6_bn; fa.bin[6]=nullptr; fa.wf[6]=ws6; fa.bf[6]=bs6; fa.O[6]=CH; fa.Ke[6]=2304; fa.ro[6]=1;
    fa.w[7]=s7_w;  fa.bn[7]=s7_bn; fa.bin[7]=nullptr; fa.wf[7]=ws7; fa.bf[7]=bs7; fa.O[7]=CH; fa.Ke[7]=512;  fa.ro[7]=0;
    fa.pq_w=pq_w; fa.pq_b=pq_b; fa.pk_w=pk_w; fa.pk_b=pk_b; fa.qkw=wqk; fa.qkb=bqk;
    fold_all_k<<<dim3(256,9),256>>>(fa);

    // ---- CoordAtt ----
    ca_pool_k<<<dim3(CH,BATCH),64>>>(x, pool);
    gemm_small<2><<<dim3(2,1,BATCH),256>>>(w1f, pool, b1f, yca,
        MIPC,128,CH, 128, 0, (long)CH*128, (long)MIPC*128);
    ca_proj_k<<<dim3(64,2,BATCH),256>>>(ca_wh, ca_bh, ca_ww, ca_bw);
    ca_apply_k<<<EB,256>>>(x, r);

    // ---- SPPCSPC (NHWC, fp16 mma) ----
    mma_gemm<1,false><<<dim3(2,32,BATCH),256,SMEMSZ>>>(r, ws1, bs1, t1,
        256,256,256,256, 256,256,0, (long)CN,0,(long)CN);
    mma_gemm<1,true ><<<dim3(2,32,BATCH),256,SMEMSZ>>>(t1, ws3, bs3, t2,
        2304,256,2304,256, 256,256,0, (long)CN,0,(long)CN);
    mma_gemm<1,false><<<dim3(2,32,BATCH),256,SMEMSZ>>>(t2, ws4, bs4, cat,
        256,256,256,1024, 256,256,0, (long)CN,0,(long)NPIX*1024);
    mp_h_k<<<EB,256>>>(cat,       mp); mp_v_k<<<EB,256>>>(mp, cat+256);
    mp_h_k<<<EB,256>>>(cat+256,   mp); mp_v_k<<<EB,256>>>(mp, cat+512);
    mp_h_k<<<EB,256>>>(cat+512,   mp); mp_v_k<<<EB,256>>>(mp, cat+768);
    mma_gemm<1,false><<<dim3(2,32,BATCH),256,SMEMSZ>>>(cat, ws5, bs5, t1,
        1024,1024,1024,256, 256,256,0, (long)NPIX*1024,0,(long)CN);
    mma_gemm<1,true ><<<dim3(2,32,BATCH),256,SMEMSZ>>>(t1, ws6, bs6, yc,
        2304,256,2304,512, 256,256,0, (long)CN,0,(long)NPIX*512);
    mma_gemm<1,false><<<dim3(2,32,BATCH),256,SMEMSZ>>>(r, ws2, bs2, yc+256,
        256,256,256,512, 256,256,0, (long)CN,0,(long)NPIX*512);
    mma_gemm<1,false><<<dim3(2,32,BATCH),256,SMEMSZ>>>(yc, ws7, bs7, res,
        512,512,512,256, 256,256,0, (long)NPIX*512,0,(long)CN);

    // ---- PAM ----
    mma_gemm<0,false><<<dim3(1,32,BATCH),256,SMEMSZ>>>(res, wqk, bqk, qk,
        256,256,256,64, 64,64,0, (long)CN,0,(long)NPIX*64);
    mma_gemm<0,false><<<dim3(32,2,BATCH),256,SMEMSZ>>>(pv_w, res, pv_b, vb,
        256,256,256,NPIX, NPIX,NPIX,1, 0,(long)CN,(long)CN);
    mma_gemm<0,false><<<dim3(32,32,BATCH),256,SMEMSZ>>>(qk, qk+32, nullptr, attn,
        CQD,64,64,NPIX, NPIX,NPIX,0, (long)NPIX*64,(long)NPIX*64,(long)NPIX*NPIX);
    softmax_row_k<<<BATCH*NPIX,256>>>(attn);
    mma_gemm<0,false><<<dim3(32,2,BATCH),256,SMEMSZ>>>(vb, attn, nullptr, pam,
        NPIX,NPIX,NPIX,NPIX, NPIX,NPIX,0, (long)CN,(long)NPIX*NPIX,(long)CN);

    // ---- CAM (split-K e) ----
    transpose_k<<<dim3(128,8,BATCH),dim3(32,8)>>>(res, resT);
    mma_gemm<0,false><<<dim3(2,2,BATCH*ESPLIT),256,SMEMSZ>>>(resT, resT, nullptr, epart,
        NPIX/ESPLIT,NPIX,NPIX,256, 256,256,0, (long)CN,(long)CN,(long)CH*CH, ESPLIT);
    e_reduce_k<<<(BATCH*CH*CH+255)/256,256>>>(epart, e);
    cam_softmax_k<<<BATCH*CH,256>>>(e, ac);
    mma_gemm<4,false><<<dim3(32,2,BATCH),256,SMEMSZ>>>(ac, res, nullptr, (float*)d_out,
        256,256,256,NPIX, NPIX,NPIX,0, (long)CH*CH,(long)CN,(long)CN,
        1, resT, pam, gpa, gca);
}

// round 6
// speedup vs baseline: 5.5448x; 1.2674x over previous
#include <cuda_runtime.h>
#include <cuda_fp16.h>
#include <cstdint>

// Problem constants
#define BATCH 2
#define CH    256
#define NPIX  4096
#define MIPC  8
#define CQD   32
#define CN    (CH*NPIX)
#define ESPLIT 8

// ===================== static scratch ==================================
__device__ float  g_pool[BATCH*CH*128];
__device__ float  g_yca [BATCH*MIPC*128];
__device__ float  g_ah  [BATCH*CH*64];
__device__ float  g_aw  [BATCH*CH*64];
__device__ __half g_r   [BATCH*CN];              // NHWC half
__device__ __half g_t1  [BATCH*CN];
__device__ __half g_t2  [BATCH*CN];
__device__ __half g_cat [(long)BATCH*NPIX*1024];
__device__ __half g_mp  [BATCH*CN];
__device__ __half g_yc  [(long)BATCH*NPIX*512];
__device__ __half g_res16[BATCH*CN];             // NHWC half (operand)
__device__ float  g_res32[BATCH*CN];             // NHWC f32 (residual)
__device__ __half g_resT16[BATCH*CN];            // NCHW half (e GEMM)
__device__ float  g_resT32[BATCH*CN];            // NCHW f32 (final residual)
__device__ __half g_qk  [BATCH*NPIX*64];
__device__ __half g_v   [BATCH*CN];              // NCHW half
__device__ __half g_attn[(long)BATCH*NPIX*NPIX]; // 64 MB half
__device__ float  g_pam [BATCH*CN];              // NCHW f32
__device__ float  g_e   [BATCH*CH*CH];
__device__ float  g_epart[BATCH*ESPLIT*CH*CH];
__device__ __half g_ac  [BATCH*CH*CH];
// folded weights (half) + biases (f32)
__device__ float  g_w1f[MIPC*CH];   __device__ float g_b1f[MIPC];
__device__ __half g_ws1[CH*CH];     __device__ float g_bs1[CH];
__device__ __half g_ws2[CH*CH];     __device__ float g_bs2[CH];
__device__ __half g_ws3[CH*2304];   __device__ float g_bs3[CH];
__device__ __half g_ws4[CH*CH];     __device__ float g_bs4[CH];
__device__ __half g_ws5[CH*1024];   __device__ float g_bs5[CH];
__device__ __half g_ws6[CH*2304];   __device__ float g_bs6[CH];
__device__ __half g_ws7[CH*512];    __device__ float g_bs7[CH];
__device__ __half g_wqk[64*CH];     __device__ float g_bqk[64];
__device__ __half g_wpv[CH*CH];

// ===================== merged fold/convert (1 launch) ==================
struct FoldArgs {
    const float* w[8]; const float* bn[8]; const float* bin[8];
    __half* wf[8]; float* bf[8];
    int O[8]; int Ke[8]; int ro[8];
    float* w1f_f;
    const float *pq_w, *pq_b, *pk_w, *pk_b, *pv_w;
    __half *qkw, *pvw;
    float *qkb;
};

__global__ void fold_all_k(FoldArgs a)
{
    int j = blockIdx.y, o = blockIdx.x;
    if (j == 8) {  // qk concat -> half
        if (o >= 64) return;
        const float* src = (o < 32) ? (a.pq_w + (long)o*256)
                                    : (a.pk_w + (long)(o-32)*256);
        for (int k = threadIdx.x; k < 256; k += blockDim.x)
            a.qkw[(long)o*256 + k] = __float2half(src[k]);
        if (threadIdx.x == 0)
            a.qkb[o] = (o < 32) ? a.pq_b[o] : a.pk_b[o-32];
        return;
    }
    if (j == 9) {  // pv weight -> half
        for (int k = threadIdx.x; k < 256; k += blockDim.x)
            a.pvw[(long)o*256 + k] = __float2half(a.pv_w[(long)o*256 + k]);
        return;
    }
    int O = a.O[j];
    if (o >= O) return;
    const float* bn = a.bn[j];
    float g  = bn[o], be = bn[O+o], mn = bn[2*O+o], vr = bn[3*O+o];
    float s = g * rsqrtf(vr + 1e-5f);
    int Ke = a.Ke[j];
    const float* w = a.w[j];
    if (j == 0) {  // CoordAtt w1: keep float
        for (int k = threadIdx.x; k < Ke; k += blockDim.x)
            a.w1f_f[(long)o*Ke + k] = w[(long)o*Ke + k] * s;
    } else if (a.ro[j]) {
        __half* wf = a.wf[j];
        for (int k = threadIdx.x; k < Ke; k += blockDim.x) {
            int t = k >> 8, ci = k & 255;
            wf[(long)o*Ke + k] = __float2half(w[((long)o*256 + ci)*9 + t] * s);
        }
    } else {
        __half* wf = a.wf[j];
        for (int k = threadIdx.x; k < Ke; k += blockDim.x)
            wf[(long)o*Ke + k] = __float2half(w[(long)o*Ke + k] * s);
    }
    if (threadIdx.x == 0)
        a.bf[j][o] = (a.bin[j] ? a.bin[j][o] : 0.f) * s + be - mn * s;
}

// ===================== fp16 mma.sync GEMM (64x64 warp tiles) ===========
__device__ __forceinline__ void mma_f16(float c[4], const uint32_t a[4],
                                        const uint32_t b[2]) {
    asm volatile(
        "mma.sync.aligned.m16n8k16.row.col.f32.f16.f16.f32 "
        "{%0,%1,%2,%3}, {%4,%5,%6,%7}, {%8,%9}, {%0,%1,%2,%3};"
        : "+f"(c[0]), "+f"(c[1]), "+f"(c[2]), "+f"(c[3])
        : "r"(a[0]), "r"(a[1]), "r"(a[2]), "r"(a[3]), "r"(b[0]), "r"(b[1]));
}

// SMEM rows: 32 halves data + 8 halves pad = 20 words
#define ROWW 20
#define STG_STRIDE (128*ROWW)
#define B_BASE (2*STG_STRIDE)
#define SMEM_WORDS (4*STG_STRIDE)      // 40 KB

template<typename OutT>
__device__ __forceinline__ void st2(OutT* p, float v0, float v1);
template<> __device__ __forceinline__ void st2<__half>(__half* p, float v0, float v1) {
    *(__half2*)p = __floats2half2_rn(v0, v1);
}
template<> __device__ __forceinline__ void st2<float>(float* p, float v0, float v1) {
    *(float2*)p = make_float2(v0, v1);
}

// D[m0..+127][n0..+127] = act( sum_k A[m][k]*B[n][k] + bias )  (half in)
// ACT: 0 none, 1 SiLU (+optional Caux f32 copy), 4 final combine
template<int ACT, bool CONV3, typename OutT>
__global__ __launch_bounds__(128) void mma_gemm(
    const __half* __restrict__ A, const __half* __restrict__ B,
    const float* __restrict__ bias, OutT* __restrict__ C,
    int K, int lda, int ldb, int ldc, int Bn, int ncols, int bias_on_m,
    long sA_, long sB_, long sC_,
    int nsplit = 1, float* __restrict__ Caux = nullptr,
    const float* __restrict__ f1 = nullptr, const float* __restrict__ f2 = nullptr,
    const float* __restrict__ gam1 = nullptr, const float* __restrict__ gam2 = nullptr)
{
    extern __shared__ uint32_t smu[];

    int bz = blockIdx.z;
    int batch = bz, slice = 0;
    if (nsplit > 1) { batch = bz / nsplit; slice = bz - batch * nsplit; }
    A += batch * sA_ + (long)slice * K;
    B += batch * sB_ + (long)slice * K;
    C += (long)bz * sC_;
    float gg1 = 0.f, gg2 = 0.f;
    if (ACT == 4) {
        f1 += (long)batch * CN; f2 += (long)batch * CN;
        gg1 = gam1[0]; gg2 = gam2[0];
    }

    int m0 = blockIdx.y * 128, n0 = blockIdx.x * 128;
    int tid = threadIdx.x;
    int lane = tid & 31, w = tid >> 5;
    int wm = w >> 1, wn = w & 1;           // 2x2 warp grid, 64x64 tiles
    int g = lane >> 2, t = lane & 3;

    float acc[4][8][4] = {};
    uint4 bufA[4], bufB[4];

    auto ldg = [&](int it) {
        int k0 = it * 32;
        if (!CONV3) {
            #pragma unroll
            for (int i = 0; i < 4; i++) {
                int f = i*128 + tid; int m = f >> 2; int v = f & 3;
                bufA[i] = *(const uint4*)(A + (long)(m0+m)*lda + k0 + v*8);
            }
        } else {
            int tap = k0 >> 8, ci0 = k0 & 255;
            int dy = tap/3 - 1, dx = tap%3 - 1;
            #pragma unroll
            for (int i = 0; i < 4; i++) {
                int f = i*128 + tid; int m = f >> 2; int v = f & 3;
                int pix = m0 + m;
                int y = (pix >> 6) + dy, x = (pix & 63) + dx;
                uint4 val = make_uint4(0,0,0,0);
                if ((unsigned)y < 64u && (unsigned)x < 64u)
                    val = *(const uint4*)(A + (long)((y<<6)+x)*lda + ci0 + v*8);
                bufA[i] = val;
            }
        }
        #pragma unroll
        for (int i = 0; i < 4; i++) {
            int f = i*128 + tid; int n = f >> 2; int v = f & 3;
            uint4 val = make_uint4(0,0,0,0);
            if (n0 + n < Bn)
                val = *(const uint4*)(B + (long)(n0+n)*ldb + k0 + v*8);
            bufB[i] = val;
        }
    };
    auto sts = [&](int s) {
        #pragma unroll
        for (int i = 0; i < 4; i++) {
            int f = i*128 + tid; int m = f >> 2; int v = f & 3;
            int off = s*STG_STRIDE + m*ROWW + v*4;
            *(uint4*)(smu + off) = bufA[i];
            *(uint4*)(smu + B_BASE + off) = bufB[i];
        }
    };
    auto compute = [&](int s) {
        #pragma unroll
        for (int ks = 0; ks < 2; ks++) {
            uint32_t af[4][4], bf[8][2];
            #pragma unroll
            for (int mt = 0; mt < 4; mt++) {
                int base = s*STG_STRIDE + (wm*64 + mt*16 + g)*ROWW + ks*8;
                af[mt][0] = smu[base + t];
                af[mt][1] = smu[base + 8*ROWW + t];
                af[mt][2] = smu[base + t + 4];
                af[mt][3] = smu[base + 8*ROWW + t + 4];
            }
            #pragma unroll
            for (int nt = 0; nt < 8; nt++) {
                int base = B_BASE + s*STG_STRIDE + (wn*64 + nt*8 + g)*ROWW + ks*8;
                bf[nt][0] = smu[base + t];
                bf[nt][1] = smu[base + t + 4];
            }
            #pragma unroll
            for (int mt = 0; mt < 4; mt++)
                #pragma unroll
                for (int nt = 0; nt < 8; nt++)
                    mma_f16(acc[mt][nt], af[mt], bf[nt]);
        }
    };

    int T = K >> 5;
    ldg(0);
    sts(0);
    __syncthreads();
    for (int it = 0; it < T; it++) {
        if (it + 1 < T) ldg(it + 1);
        compute(it & 1);
        if (it + 1 < T) {
            __syncthreads();
            sts((it + 1) & 1);
            __syncthreads();
        }
    }

    // epilogue
    int valid = ncols - n0; if (valid > 128) valid = 128;
    #pragma unroll
    for (int mt = 0; mt < 4; mt++) {
        #pragma unroll
        for (int half_ = 0; half_ < 2; half_++) {
            int m = m0 + wm*64 + mt*16 + g + half_*8;
            float bm = (bias && bias_on_m) ? bias[m] : 0.f;
            long base = (long)m*ldc + n0;
            #pragma unroll
            for (int nt = 0; nt < 8; nt++) {
                int nl = wn*64 + nt*8 + 2*t;
                if (nl >= valid) continue;
                float v0 = acc[mt][nt][half_*2 + 0] + bm;
                float v1 = acc[mt][nt][half_*2 + 1] + bm;
                if (bias && !bias_on_m) { v0 += bias[n0+nl]; v1 += bias[n0+nl+1]; }
                if (ACT == 1) {
                    v0 = v0 / (1.f + __expf(-v0));
                    v1 = v1 / (1.f + __expf(-v1));
                    if (Caux) *(float2*)(Caux + (long)bz*sC_ + base + nl)
                              = make_float2(v0, v1);
                } else if (ACT == 4) {
                    float2 r1 = *(const float2*)(f1 + base + nl);
                    float2 r2 = *(const float2*)(f2 + base + nl);
                    v0 = 3.f*r1.x + gg1*r2.x + gg2*v0;
                    v1 = 3.f*r1.y + gg1*r2.y + gg2*v1;
                }
                st2<OutT>(C + base + nl, v0, v1);
            }
        }
    }
}

// ===================== small FMA GEMM (CoordAtt yca only) =============
__global__ __launch_bounds__(256) void gemm_small_hsw(
    const float* __restrict__ A, const float* __restrict__ B,
    const float* __restrict__ bias, float* __restrict__ C,
    int M, int N, int K, int ldb, long sB, long sC)
{
    int b = blockIdx.z;
    B += (long)b*sB; C += (long)b*sC;
    int m0 = blockIdx.y*64, n0 = blockIdx.x*64;
    __shared__ float As[16][64], Bs[16][65];
    int tid = threadIdx.x, tx = tid & 15, ty = tid >> 4;
    float acc[4][4] = {};
    for (int k0 = 0; k0 < K; k0 += 16) {
        int i = tid >> 2, jb = (tid & 3)*4, mI = m0 + i;
        #pragma unroll
        for (int j = 0; j < 4; j++) {
            int k = k0 + jb + j;
            As[jb+j][i] = (mI < M && k < K) ? A[(long)mI*K + k] : 0.f;
        }
        int jr = tid >> 4, nb = (tid & 15)*4, k = k0 + jr;
        #pragma unroll
        for (int n = 0; n < 4; n++) {
            int nn = n0 + nb + n;
            Bs[jr][nb+n] = (k < K && nn < N) ? B[(long)k*ldb + nn] : 0.f;
        }
        __syncthreads();
        #pragma unroll
        for (int j = 0; j < 16; j++) {
            float a[4], bb[4];
            #pragma unroll
            for (int i2 = 0; i2 < 4; i2++) a[i2]  = As[j][ty*4+i2];
            #pragma unroll
            for (int i2 = 0; i2 < 4; i2++) bb[i2] = Bs[j][tx*4+i2];
            #pragma unroll
            for (int i2 = 0; i2 < 4; i2++)
                #pragma unroll
                for (int jj = 0; jj < 4; jj++) acc[i2][jj] += a[i2]*bb[jj];
        }
        __syncthreads();
    }
    #pragma unroll
    for (int i = 0; i < 4; i++) {
        int mI = m0 + ty*4 + i;
        if (mI >= M) continue;
        float bv = bias ? bias[mI] : 0.f;
        #pragma unroll
        for (int jj = 0; jj < 4; jj++) {
            int n = n0 + tx*4 + jj;
            if (n >= N) continue;
            float v = acc[i][jj] + bv;
            float tq = fminf(fmaxf(v+3.f,0.f),6.f); v = v*tq*(1.f/6.f);  // h-swish
            C[(long)mI*N + n] = v;
        }
    }
}

// ===================== CoordAtt glue ==================================
__global__ void ca_pool_k(const float* __restrict__ x, float* __restrict__ pool)
{
    int c = blockIdx.x, b = blockIdx.y, t = threadIdx.x;
    const float* p = x + ((long)b*CH + c)*NPIX;
    float sh = 0.f, sw = 0.f;
    for (int i = 0; i < 64; i++) sh += p[t*64 + i];
    for (int i = 0; i < 64; i++) sw += p[i*64 + t];
    float* o = pool + ((long)b*CH + c)*128;
    o[t] = sh*(1.f/64.f); o[64+t] = sw*(1.f/64.f);
}

__global__ void ca_proj_k(const float* __restrict__ wh, const float* __restrict__ bh,
                          const float* __restrict__ ww, const float* __restrict__ bw)
{
    int hw = blockIdx.y, b = blockIdx.z;
    int idx = blockIdx.x*256 + threadIdx.x;
    int c = idx >> 6, pos = idx & 63;
    const float* W  = hw ? ww : wh;
    const float* Bi = hw ? bw : bh;
    const float* y  = g_yca + (long)b*MIPC*128 + (hw ? 64 : 0) + pos;
    float s = Bi[c];
    #pragma unroll
    for (int i = 0; i < MIPC; i++) s += W[c*MIPC + i] * y[i*128];
    float o = 1.f / (1.f + __expf(-s));
    float* dst = hw ? g_aw : g_ah;
    dst[((long)b*CH + c)*64 + pos] = o;
}

__global__ void ca_apply_k(const float* __restrict__ x)
{
    long i = blockIdx.x*256L + threadIdx.x;
    if (i >= (long)BATCH*CN) return;
    int c = (int)(i & 255); long t = i >> 8;
    int pix = (int)(t & 4095); int b = (int)(t >> 12);
    long bc = (long)b*CH + c;
    int y = pix >> 6, xx = pix & 63;
    g_r[i] = __float2half(
        x[(long)b*CN + (long)c*NPIX + pix] * g_aw[bc*64+xx] * g_ah[bc*64+y]);
}

// ===================== separable maxpool (half2) =======================
__global__ void mp_h_k(const __half* __restrict__ src, __half* __restrict__ tmp)
{
    long i = blockIdx.x*256L + threadIdx.x;       // BATCH*NPIX*128 half2
    if (i >= (long)BATCH*NPIX*128) return;
    int c2 = (int)(i & 127); long t = i >> 7;
    int pix = (int)(t & 4095); int b = (int)(t >> 12);
    int y = pix >> 6, x = pix & 63;
    const __half2* s = (const __half2*)(src + (long)b*NPIX*1024) ;
    __half2 m = __float2half2_rn(-65504.f);
    #pragma unroll
    for (int d = -2; d <= 2; d++) {
        int xx = x + d;
        if ((unsigned)xx < 64u) m = __hmax2(m, s[(long)((y<<6)+xx)*512 + c2]);
    }
    ((__half2*)(tmp + (long)b*CN))[(long)pix*128 + c2] = m;
}
__global__ void mp_v_k(const __half* __restrict__ tmp, __half* __restrict__ dst)
{
    long i = blockIdx.x*256L + threadIdx.x;
    if (i >= (long)BATCH*NPIX*128) return;
    int c2 = (int)(i & 127); long t = i >> 7;
    int pix = (int)(t & 4095); int b = (int)(t >> 12);
    int y = pix >> 6, x = pix & 63;
    const __half2* s = (const __half2*)(tmp + (long)b*CN);
    __half2 m = __float2half2_rn(-65504.f);
    #pragma unroll
    for (int d = -2; d <= 2; d++) {
        int yy = y + d;
        if ((unsigned)yy < 64u) m = __hmax2(m, s[(long)((yy<<6)+x)*128 + c2]);
    }
    ((__half2*)(dst + (long)b*NPIX*1024))[(long)pix*512 + c2] = m;
}

// ===================== PAM softmax (half rows of 4096) =================
__global__ void softmax_row_k(__half* __restrict__ a)
{
    __half2* p = (__half2*)(a + (long)blockIdx.x * 4096);
    int t = threadIdx.x;
    __shared__ float red[256];
    float2 v[8];
    #pragma unroll
    for (int i = 0; i < 8; i++) v[i] = __half22float2(p[t + i*256]);
    float mx = v[0].x;
    #pragma unroll
    for (int i = 0; i < 8; i++) { mx = fmaxf(mx, v[i].x); mx = fmaxf(mx, v[i].y); }
    red[t] = mx; __syncthreads();
    for (int s = 128; s > 0; s >>= 1) { if (t < s) red[t] = fmaxf(red[t], red[t+s]); __syncthreads(); }
    mx = red[0]; __syncthreads();
    float sum = 0.f;
    #pragma unroll
    for (int i = 0; i < 8; i++) {
        v[i].x = __expf(v[i].x - mx); v[i].y = __expf(v[i].y - mx);
        sum += v[i].x + v[i].y;
    }
    red[t] = sum; __syncthreads();
    for (int s = 128; s > 0; s >>= 1) { if (t < s) red[t] += red[t+s]; __syncthreads(); }
    float inv = 1.f / red[0];
    #pragma unroll
    for (int i = 0; i < 8; i++)
        p[t + i*256] = __floats2half2_rn(v[i].x * inv, v[i].y * inv);
}

// ===================== CAM: split-K reduce + softmax ===================
__global__ void e_reduce_k(const float* __restrict__ ep, float* __restrict__ e)
{
    int i = blockIdx.x*256 + threadIdx.x;
    int b = i >> 16, r = i & 65535;
    float s = 0.f;
    #pragma unroll
    for (int k = 0; k < ESPLIT; k++)
        s += ep[((long)(b*ESPLIT + k) << 16) + r];
    e[i] = s;
}

__global__ void cam_softmax_k(const float* __restrict__ e, __half* __restrict__ ac)
{
    long row = blockIdx.x;
    const float* p = e + row*256;
    int t = threadIdx.x;
    __shared__ float sm[256];
    float v = p[t];
    sm[t] = v; __syncthreads();
    for (int s = 128; s > 0; s >>= 1) { if (t < s) sm[t] = fmaxf(sm[t], sm[t+s]); __syncthreads(); }
    float rowmax = sm[0]; __syncthreads();
    float z = rowmax - v;
    sm[t] = z; __syncthreads();
    for (int s = 128; s > 0; s >>= 1) { if (t < s) sm[t] = fmaxf(sm[t], sm[t+s]); __syncthreads(); }
    float zm = sm[0]; __syncthreads();
    float pe = __expf(z - zm);
    sm[t] = pe; __syncthreads();
    for (int s = 128; s > 0; s >>= 1) { if (t < s) sm[t] += sm[t+s]; __syncthreads(); }
    ac[row*256 + t] = __float2half(pe / sm[0]);
}

// ============ tiled transpose NHWC(f32) -> NCHW f32 + half =============
__global__ void transpose_k(const float* __restrict__ src)
{
    __shared__ float s[32][33];
    int b = blockIdx.z;
    int p0 = blockIdx.x*32, c0 = blockIdx.y*32;
    int tx = threadIdx.x, ty = threadIdx.y;  // 32 x 8
    const float* S = src + (long)b*CN;
    float*  D32 = g_resT32 + (long)b*CN;
    __half* D16 = g_resT16 + (long)b*CN;
    #pragma unroll
    for (int j = 0; j < 32; j += 8)
        s[ty+j][tx] = S[(long)(p0+ty+j)*256 + c0+tx];
    __syncthreads();
    #pragma unroll
    for (int j = 0; j < 32; j += 8) {
        float v = s[tx][ty+j];
        long o = (long)(c0+ty+j)*4096 + p0+tx;
        D32[o] = v;
        D16[o] = __float2half(v);
    }
}

// ======================================================================
extern "C" void kernel_launch(void* const* d_in, const int* in_sizes, int n_in,
                              void* d_out, int out_size)
{
    const float* x     = (const float*)d_in[0];
    const float* ca_w1 = (const float*)d_in[1];
    const float* ca_b1 = (const float*)d_in[2];
    const float* ca_bn = (const float*)d_in[3];
    const float* ca_wh = (const float*)d_in[4];
    const float* ca_bh = (const float*)d_in[5];
    const float* ca_ww = (const float*)d_in[6];
    const float* ca_bw = (const float*)d_in[7];
    const float* s1_w  = (const float*)d_in[8];  const float* s1_bn = (const float*)d_in[9];
    const float* s2_w  = (const float*)d_in[10]; const float* s2_bn = (const float*)d_in[11];
    const float* s3_w  = (const float*)d_in[12]; const float* s3_bn = (const float*)d_in[13];
    const float* s4_w  = (const float*)d_in[14]; const float* s4_bn = (const float*)d_in[15];
    const float* s5_w  = (const float*)d_in[16]; const float* s5_bn = (const float*)d_in[17];
    const float* s6_w  = (const float*)d_in[18]; const float* s6_bn = (const float*)d_in[19];
    const float* s7_w  = (const float*)d_in[20]; const float* s7_bn = (const float*)d_in[21];
    const float* pq_w  = (const float*)d_in[22]; const float* pq_b  = (const float*)d_in[23];
    const float* pk_w  = (const float*)d_in[24]; const float* pk_b  = (const float*)d_in[25];
    const float* pv_w  = (const float*)d_in[26]; const float* pv_b  = (const float*)d_in[27];
    const float* gpa   = (const float*)d_in[28];
    const float* gca   = (const float*)d_in[29];

    float *pool,*yca,*res32,*pam,*e,*epart,*w1f,*b1f,*bs1,*bs2,*bs3,*bs4,*bs5,*bs6,*bs7,*bqk;
    __half *r16,*t1,*t2,*cat,*mp,*yc,*res16,*resT16,*qk,*vb,*attn,*ac;
    __half *ws1,*ws2,*ws3,*ws4,*ws5,*ws6,*ws7,*wqk,*wpv;
    float *resT32;
    cudaGetSymbolAddress((void**)&pool, g_pool);    cudaGetSymbolAddress((void**)&yca, g_yca);
    cudaGetSymbolAddress((void**)&r16, g_r);        cudaGetSymbolAddress((void**)&t1, g_t1);
    cudaGetSymbolAddress((void**)&t2, g_t2);        cudaGetSymbolAddress((void**)&cat, g_cat);
    cudaGetSymbolAddress((void**)&mp, g_mp);        cudaGetSymbolAddress((void**)&yc, g_yc);
    cudaGetSymbolAddress((void**)&res16, g_res16);  cudaGetSymbolAddress((void**)&res32, g_res32);
    cudaGetSymbolAddress((void**)&resT16, g_resT16);cudaGetSymbolAddress((void**)&resT32, g_resT32);
    cudaGetSymbolAddress((void**)&qk, g_qk);        cudaGetSymbolAddress((void**)&vb, g_v);
    cudaGetSymbolAddress((void**)&attn, g_attn);    cudaGetSymbolAddress((void**)&pam, g_pam);
    cudaGetSymbolAddress((void**)&e, g_e);          cudaGetSymbolAddress((void**)&epart, g_epart);
    cudaGetSymbolAddress((void**)&ac, g_ac);
    cudaGetSymbolAddress((void**)&w1f, g_w1f);      cudaGetSymbolAddress((void**)&b1f, g_b1f);
    cudaGetSymbolAddress((void**)&ws1, g_ws1);      cudaGetSymbolAddress((void**)&bs1, g_bs1);
    cudaGetSymbolAddress((void**)&ws2, g_ws2);      cudaGetSymbolAddress((void**)&bs2, g_bs2);
    cudaGetSymbolAddress((void**)&ws3, g_ws3);      cudaGetSymbolAddress((void**)&bs3, g_bs3);
    cudaGetSymbolAddress((void**)&ws4, g_ws4);      cudaGetSymbolAddress((void**)&bs4, g_bs4);
    cudaGetSymbolAddress((void**)&ws5, g_ws5);      cudaGetSymbolAddress((void**)&bs5, g_bs5);
    cudaGetSymbolAddress((void**)&ws6, g_ws6);      cudaGetSymbolAddress((void**)&bs6, g_bs6);
    cudaGetSymbolAddress((void**)&ws7, g_ws7);      cudaGetSymbolAddress((void**)&bs7, g_bs7);
    cudaGetSymbolAddress((void**)&wqk, g_wqk);      cudaGetSymbolAddress((void**)&bqk, g_bqk);
    cudaGetSymbolAddress((void**)&wpv, g_wpv);

    const int SMEMSZ = SMEM_WORDS * 4;   // 40960 B
    cudaFuncSetAttribute(mma_gemm<0,false,__half>, cudaFuncAttributeMaxDynamicSharedMemorySize, SMEMSZ);
    cudaFuncSetAttribute(mma_gemm<0,false,float>,  cudaFuncAttributeMaxDynamicSharedMemorySize, SMEMSZ);
    cudaFuncSetAttribute(mma_gemm<1,false,__half>, cudaFuncAttributeMaxDynamicSharedMemorySize, SMEMSZ);
    cudaFuncSetAttribute(mma_gemm<1,true,__half>,  cudaFuncAttributeMaxDynamicSharedMemorySize, SMEMSZ);
    cudaFuncSetAttribute(mma_gemm<4,false,float>,  cudaFuncAttributeMaxDynamicSharedMemorySize, SMEMSZ);

    const int EB  = (BATCH*CN + 255)/256;
    const int EB2 = (BATCH*NPIX*128 + 255)/256;

    // ---- merged fold/convert ----
    FoldArgs fa;
    fa.w[0]=ca_w1; fa.bn[0]=ca_bn; fa.bin[0]=ca_b1; fa.wf[0]=nullptr; fa.bf[0]=b1f; fa.O[0]=MIPC; fa.Ke[0]=256;  fa.ro[0]=0;
    fa.w[1]=s1_w;  fa.bn[1]=s1_bn; fa.bin[1]=nullptr; fa.wf[1]=ws1; fa.bf[1]=bs1; fa.O[1]=CH; fa.Ke[1]=256;  fa.ro[1]=0;
    fa.w[2]=s2_w;  fa.bn[2]=s2_bn; fa.bin[2]=nullptr; fa.wf[2]=ws2; fa.bf[2]=bs2; fa.O[2]=CH; fa.Ke[2]=256;  fa.ro[2]=0;
    fa.w[3]=s3_w;  fa.bn[3]=s3_bn; fa.bin[3]=nullptr; fa.wf[3]=ws3; fa.bf[3]=bs3; fa.O[3]=CH; fa.Ke[3]=2304; fa.ro[3]=1;
    fa.w[4]=s4_w;  fa.bn[4]=s4_bn; fa.bin[4]=nullptr; fa.wf[4]=ws4; fa.bf[4]=bs4; fa.O[4]=CH; fa.Ke[4]=256;  fa.ro[4]=0;
    fa.w[5]=s5_w;  fa.bn[5]=s5_bn; fa.bin[5]=nullptr; fa.wf[5]=ws5; fa.bf[5]=bs5; fa.O[5]=CH; fa.Ke[5]=1024; fa.ro[5]=0;
    fa.w[6]=s6_w;  fa.bn[6]=s6_bn; fa.bin[6]=nullptr; fa.wf[6]=ws6; fa.bf[6]=bs6; fa.O[6]=CH; fa.Ke[6]=2304; fa.ro[6]=1;
    fa.w[7]=s7_w;  fa.bn[7]=s7_bn; fa.bin[7]=nullptr; fa.wf[7]=ws7; fa.bf[7]=bs7; fa.O[7]=CH; fa.Ke[7]=512;  fa.ro[7]=0;
    fa.w1f_f=w1f;
    fa.pq_w=pq_w; fa.pq_b=pq_b; fa.pk_w=pk_w; fa.pk_b=pk_b; fa.pv_w=pv_w;
    fa.qkw=wqk; fa.qkb=bqk; fa.pvw=wpv;
    fold_all_k<<<dim3(256,10),256>>>(fa);

    // ---- CoordAtt ----
    ca_pool_k<<<dim3(CH,BATCH),64>>>(x, pool);
    gemm_small_hsw<<<dim3(2,1,BATCH),256>>>(w1f, pool, b1f, yca,
        MIPC,128,CH, 128, (long)CH*128, (long)MIPC*128);
    ca_proj_k<<<dim3(64,2,BATCH),256>>>(ca_wh, ca_bh, ca_ww, ca_bw);
    ca_apply_k<<<EB,256>>>(x);

    // ---- SPPCSPC ----
    mma_gemm<1,false,__half><<<dim3(2,32,BATCH),128,SMEMSZ>>>(r16, ws1, bs1, t1,
        256,256,256,256, 256,256,0, (long)CN,0,(long)CN);
    mma_gemm<1,true,__half><<<dim3(2,32,BATCH),128,SMEMSZ>>>(t1, ws3, bs3, t2,
        2304,256,2304,256, 256,256,0, (long)CN,0,(long)CN);
    mma_gemm<1,false,__half><<<dim3(2,32,BATCH),128,SMEMSZ>>>(t2, ws4, bs4, cat,
        256,256,256,1024, 256,256,0, (long)CN,0,(long)NPIX*1024);
    mp_h_k<<<EB2,256>>>(cat,       mp); mp_v_k<<<EB2,256>>>(mp, cat+256);
    mp_h_k<<<EB2,256>>>(cat+256,   mp); mp_v_k<<<EB2,256>>>(mp, cat+512);
    mp_h_k<<<EB2,256>>>(cat+512,   mp); mp_v_k<<<EB2,256>>>(mp, cat+768);
    mma_gemm<1,false,__half><<<dim3(2,32,BATCH),128,SMEMSZ>>>(cat, ws5, bs5, t1,
        1024,1024,1024,256, 256,256,0, (long)NPIX*1024,0,(long)CN);
    mma_gemm<1,true,__half><<<dim3(2,32,BATCH),128,SMEMSZ>>>(t1, ws6, bs6, yc,
        2304,256,2304,512, 256,256,0, (long)CN,0,(long)NPIX*512);
    mma_gemm<1,false,__half><<<dim3(2,32,BATCH),128,SMEMSZ>>>(r16, ws2, bs2, yc+256,
        256,256,256,512, 256,256,0, (long)CN,0,(long)NPIX*512);
    // s7: half out + f32 aux (residual path)
    mma_gemm<1,false,__half><<<dim3(2,32,BATCH),128,SMEMSZ>>>(yc, ws7, bs7, res16,
        512,512,512,256, 256,256,0, (long)NPIX*512,0,(long)CN, 1, res32);

    // ---- PAM ----
    mma_gemm<0,false,__half><<<dim3(1,32,BATCH),128,SMEMSZ>>>(res16, wqk, bqk, qk,
        256,256,256,64, 64,64,0, (long)CN,0,(long)NPIX*64);
    mma_gemm<0,false,__half><<<dim3(32,2,BATCH),128,SMEMSZ>>>(wpv, res16, pv_b, vb,
        256,256,256,NPIX, NPIX,NPIX,1, 0,(long)CN,(long)CN);
    mma_gemm<0,false,__half><<<dim3(32,32,BATCH),128,SMEMSZ>>>(qk, qk+32, nullptr, attn,
        CQD,64,64,NPIX, NPIX,NPIX,0, (long)NPIX*64,(long)NPIX*64,(long)NPIX*NPIX);
    softmax_row_k<<<BATCH*NPIX,256>>>(attn);
    mma_gemm<0,false,float><<<dim3(32,2,BATCH),128,SMEMSZ>>>(vb, attn, nullptr, pam,
        NPIX,NPIX,NPIX,NPIX, NPIX,NPIX,0, (long)CN,(long)NPIX*NPIX,(long)CN);

    // ---- CAM ----
    transpose_k<<<dim3(128,8,BATCH),dim3(32,8)>>>(res32);
    mma_gemm<0,false,float><<<dim3(2,2,BATCH*ESPLIT),128,SMEMSZ>>>(resT16, resT16, nullptr, epart,
        NPIX/ESPLIT,NPIX,NPIX,256, 256,256,0, (long)CN,(long)CN,(long)CH*CH, ESPLIT);
    e_reduce_k<<<(BATCH*CH*CH+255)/256,256>>>(epart, e);
    cam_softmax_k<<<BATCH*CH,256>>>(e, ac);
    mma_gemm<4,false,float><<<dim3(32,2,BATCH),128,SMEMSZ>>>(ac, res16, nullptr, (float*)d_out,
        256,256,256,NPIX, NPIX,NPIX,0, (long)CH*CH,(long)CN,(long)CN,
        1, nullptr, resT32, pam, gpa, gca);
}

// round 7
// speedup vs baseline: 6.0548x; 1.0920x over previous
#include <cuda_runtime.h>
#include <cuda_fp16.h>
#include <cstdint>

// Problem constants
#define BATCH 2
#define CH    256
#define NPIX  4096
#define MIPC  8
#define CQD   32
#define CN    (CH*NPIX)
#define ESPLIT 8

// ===================== static scratch ==================================
__device__ float  g_pool[BATCH*CH*128];
__device__ float  g_yca [BATCH*MIPC*128];
__device__ float  g_ah  [BATCH*CH*64];
__device__ float  g_aw  [BATCH*CH*64];
__device__ __half g_r   [BATCH*CN];              // NHWC half
__device__ __half g_t1  [BATCH*CN];
__device__ __half g_t2  [BATCH*CN];
__device__ __half g_cat [(long)BATCH*NPIX*1024];
__device__ __half g_yc  [(long)BATCH*NPIX*512];
__device__ __half g_res16[BATCH*CN];             // NHWC half (operand)
__device__ float  g_res32[BATCH*CN];             // NHWC f32 (residual)
__device__ __half g_resT16[BATCH*CN];            // NCHW half (e GEMM)
__device__ float  g_resT32[BATCH*CN];            // NCHW f32 (final residual)
__device__ __half g_qk  [BATCH*NPIX*64];
__device__ __half g_v   [BATCH*CN];              // NCHW half
__device__ __half g_attn[(long)BATCH*NPIX*NPIX]; // 64 MB half
__device__ float  g_pam [BATCH*CN];              // NCHW f32
__device__ float  g_e   [BATCH*CH*CH];
__device__ float  g_epart[BATCH*ESPLIT*CH*CH];
__device__ __half g_ac  [BATCH*CH*CH];
// folded weights (half) + biases (f32)
__device__ float  g_w1f[MIPC*CH];   __device__ float g_b1f[MIPC];
__device__ __half g_ws1[CH*CH];     __device__ float g_bs1[CH];
__device__ __half g_ws2[CH*CH];     __device__ float g_bs2[CH];
__device__ __half g_ws3[CH*2304];   __device__ float g_bs3[CH];
__device__ __half g_ws4[CH*CH];     __device__ float g_bs4[CH];
__device__ __half g_ws5[CH*1024];   __device__ float g_bs5[CH];
__device__ __half g_ws6[CH*2304];   __device__ float g_bs6[CH];
__device__ __half g_ws7[CH*512];    __device__ float g_bs7[CH];
__device__ __half g_wqk[64*CH];     __device__ float g_bqk[64];
__device__ __half g_wpv[CH*CH];

// ===================== merged fold/convert (1 launch) ==================
struct FoldArgs {
    const float* w[8]; const float* bn[8]; const float* bin[8];
    __half* wf[8]; float* bf[8];
    int O[8]; int Ke[8]; int ro[8];
    float* w1f_f;
    const float *pq_w, *pq_b, *pk_w, *pk_b, *pv_w;
    __half *qkw, *pvw;
    float *qkb;
};

__global__ void fold_all_k(FoldArgs a)
{
    int j = blockIdx.y, o = blockIdx.x;
    if (j == 8) {
        if (o >= 64) return;
        const float* src = (o < 32) ? (a.pq_w + (long)o*256)
                                    : (a.pk_w + (long)(o-32)*256);
        for (int k = threadIdx.x; k < 256; k += blockDim.x)
            a.qkw[(long)o*256 + k] = __float2half(src[k]);
        if (threadIdx.x == 0)
            a.qkb[o] = (o < 32) ? a.pq_b[o] : a.pk_b[o-32];
        return;
    }
    if (j == 9) {
        for (int k = threadIdx.x; k < 256; k += blockDim.x)
            a.pvw[(long)o*256 + k] = __float2half(a.pv_w[(long)o*256 + k]);
        return;
    }
    int O = a.O[j];
    if (o >= O) return;
    const float* bn = a.bn[j];
    float g  = bn[o], be = bn[O+o], mn = bn[2*O+o], vr = bn[3*O+o];
    float s = g * rsqrtf(vr + 1e-5f);
    int Ke = a.Ke[j];
    const float* w = a.w[j];
    if (j == 0) {
        for (int k = threadIdx.x; k < Ke; k += blockDim.x)
            a.w1f_f[(long)o*Ke + k] = w[(long)o*Ke + k] * s;
    } else if (a.ro[j]) {
        __half* wf = a.wf[j];
        for (int k = threadIdx.x; k < Ke; k += blockDim.x) {
            int t = k >> 8, ci = k & 255;
            wf[(long)o*Ke + k] = __float2half(w[((long)o*256 + ci)*9 + t] * s);
        }
    } else {
        __half* wf = a.wf[j];
        for (int k = threadIdx.x; k < Ke; k += blockDim.x)
            wf[(long)o*Ke + k] = __float2half(w[(long)o*Ke + k] * s);
    }
    if (threadIdx.x == 0)
        a.bf[j][o] = (a.bin[j] ? a.bin[j][o] : 0.f) * s + be - mn * s;
}

// ===================== fp16 mma.sync GEMM (cp.async 3-stage) ===========
__device__ __forceinline__ void mma_f16(float c[4], const uint32_t a[4],
                                        const uint32_t b[2]) {
    asm volatile(
        "mma.sync.aligned.m16n8k16.row.col.f32.f16.f16.f32 "
        "{%0,%1,%2,%3}, {%4,%5,%6,%7}, {%8,%9}, {%0,%1,%2,%3};"
        : "+f"(c[0]), "+f"(c[1]), "+f"(c[2]), "+f"(c[3])
        : "r"(a[0]), "r"(a[1]), "r"(a[2]), "r"(a[3]), "r"(b[0]), "r"(b[1]));
}
__device__ __forceinline__ void cp16(uint32_t dst, const void* src, int srcsize) {
    asm volatile("cp.async.cg.shared.global [%0], [%1], 16, %2;"
                 :: "r"(dst), "l"(src), "r"(srcsize));
}
#define CP_COMMIT() asm volatile("cp.async.commit_group;" ::: "memory")
#define CP_WAIT1()  asm volatile("cp.async.wait_group 1;" ::: "memory")

// SMEM rows: 32 halves data + 8 halves pad = 20 words
#define ROWW 20
#define HSTG (128*ROWW)          // 2560 words: one operand, one stage
#define STG2 (2*HSTG)            // A+B per stage
#define NSTG 3
#define SMEM_WORDS (NSTG*STG2)   // 15360 words = 60 KB

template<typename OutT>
__device__ __forceinline__ void st2(OutT* p, float v0, float v1);
template<> __device__ __forceinline__ void st2<__half>(__half* p, float v0, float v1) {
    *(__half2*)p = __floats2half2_rn(v0, v1);
}
template<> __device__ __forceinline__ void st2<float>(float* p, float v0, float v1) {
    *(float2*)p = make_float2(v0, v1);
}

// D[m0..+127][n0..+127] = act( sum_k A[m][k]*B[n][k] + bias )  (half in)
// ACT: 0 none, 1 SiLU (+optional Caux f32 copy), 4 final combine
template<int ACT, bool CONV3, typename OutT>
__global__ __launch_bounds__(128) void mma_gemm(
    const __half* __restrict__ A, const __half* __restrict__ B,
    const float* __restrict__ bias, OutT* __restrict__ C,
    int K, int lda, int ldb, int ldc, int Bn, int ncols, int bias_on_m,
    long sA_, long sB_, long sC_,
    int nsplit = 1, float* __restrict__ Caux = nullptr,
    const float* __restrict__ f1 = nullptr, const float* __restrict__ f2 = nullptr,
    const float* __restrict__ gam1 = nullptr, const float* __restrict__ gam2 = nullptr)
{
    extern __shared__ uint32_t smu[];
    uint32_t sbase = (uint32_t)__cvta_generic_to_shared(smu);

    int bz = blockIdx.z;
    int batch = bz, slice = 0;
    if (nsplit > 1) { batch = bz / nsplit; slice = bz - batch * nsplit; }
    A += batch * sA_ + (long)slice * K;
    B += batch * sB_ + (long)slice * K;
    C += (long)bz * sC_;
    float gg1 = 0.f, gg2 = 0.f;
    if (ACT == 4) {
        f1 += (long)batch * CN; f2 += (long)batch * CN;
        gg1 = gam1[0]; gg2 = gam2[0];
    }

    int m0 = blockIdx.y * 128, n0 = blockIdx.x * 128;
    int tid = threadIdx.x;
    int lane = tid & 31, w = tid >> 5;
    int wm = w >> 1, wn = w & 1;           // 2x2 warp grid, 64x64 tiles
    int g = lane >> 2, t = lane & 3;

    float acc[4][8][4] = {};

    // per-thread fixed load geometry: 4 A rows + 4 B rows, 16B each
    int lrow = tid >> 2, lv = tid & 3;     // row 0..31 (+i*32), vec 0..3
    int T = K >> 5;

    auto issue = [&](int it) {
        int s = it % NSTG;
        int k0 = it * 32;
        uint32_t ab = sbase + (s*STG2)*4;
        uint32_t bb = ab + HSTG*4;
        if (!CONV3) {
            #pragma unroll
            for (int i = 0; i < 4; i++) {
                int m = i*32 + lrow;
                cp16(ab + ((m*ROWW + lv*4)*4),
                     A + (long)(m0+m)*lda + k0 + lv*8, 16);
            }
        } else {
            int tap = k0 >> 8, ci0 = k0 & 255;
            int dy = tap/3 - 1, dx = tap%3 - 1;
            #pragma unroll
            for (int i = 0; i < 4; i++) {
                int m = i*32 + lrow;
                int pix = m0 + m;
                int y = (pix >> 6) + dy, x = (pix & 63) + dx;
                bool ok = ((unsigned)y < 64u) && ((unsigned)x < 64u);
                const __half* src = ok ? (A + (long)((y<<6)+x)*lda + ci0 + lv*8) : A;
                cp16(ab + ((m*ROWW + lv*4)*4), src, ok ? 16 : 0);
            }
        }
        #pragma unroll
        for (int i = 0; i < 4; i++) {
            int n = i*32 + lrow;
            bool ok = (n0 + n) < Bn;
            const __half* src = ok ? (B + (long)(n0+n)*ldb + k0 + lv*8) : B;
            cp16(bb + ((n*ROWW + lv*4)*4), src, ok ? 16 : 0);
        }
        CP_COMMIT();
    };

    auto compute = [&](int s) {
        #pragma unroll
        for (int ks = 0; ks < 2; ks++) {
            uint32_t af[4][4], bf[8][2];
            #pragma unroll
            for (int mt = 0; mt < 4; mt++) {
                int base = s*STG2 + (wm*64 + mt*16 + g)*ROWW + ks*8;
                af[mt][0] = smu[base + t];
                af[mt][1] = smu[base + 8*ROWW + t];
                af[mt][2] = smu[base + t + 4];
                af[mt][3] = smu[base + 8*ROWW + t + 4];
            }
            #pragma unroll
            for (int nt = 0; nt < 8; nt++) {
                int base = s*STG2 + HSTG + (wn*64 + nt*8 + g)*ROWW + ks*8;
                bf[nt][0] = smu[base + t];
                bf[nt][1] = smu[base + t + 4];
            }
            #pragma unroll
            for (int mt = 0; mt < 4; mt++)
                #pragma unroll
                for (int nt = 0; nt < 8; nt++)
                    mma_f16(acc[mt][nt], af[mt], bf[nt]);
        }
    };

    // prologue: 2 committed groups (pad with empty groups if T small)
    issue(0);
    if (T > 1) issue(1); else CP_COMMIT();

    for (int it = 0; it < T; it++) {
        CP_WAIT1();            // stage `it` landed
        __syncthreads();       // all warps done with slot being overwritten
        if (it + 2 < T) issue(it + 2); else CP_COMMIT();
        compute(it % NSTG);
    }

    // epilogue
    int valid = ncols - n0; if (valid > 128) valid = 128;
    #pragma unroll
    for (int mt = 0; mt < 4; mt++) {
        #pragma unroll
        for (int half_ = 0; half_ < 2; half_++) {
            int m = m0 + wm*64 + mt*16 + g + half_*8;
            float bm = (bias && bias_on_m) ? bias[m] : 0.f;
            long base = (long)m*ldc + n0;
            #pragma unroll
            for (int nt = 0; nt < 8; nt++) {
                int nl = wn*64 + nt*8 + 2*t;
                if (nl >= valid) continue;
                float v0 = acc[mt][nt][half_*2 + 0] + bm;
                float v1 = acc[mt][nt][half_*2 + 1] + bm;
                if (bias && !bias_on_m) { v0 += bias[n0+nl]; v1 += bias[n0+nl+1]; }
                if (ACT == 1) {
                    v0 = v0 / (1.f + __expf(-v0));
                    v1 = v1 / (1.f + __expf(-v1));
                    if (Caux) *(float2*)(Caux + (long)bz*sC_ + base + nl)
                              = make_float2(v0, v1);
                } else if (ACT == 4) {
                    float2 r1 = *(const float2*)(f1 + base + nl);
                    float2 r2 = *(const float2*)(f2 + base + nl);
                    v0 = 3.f*r1.x + gg1*r2.x + gg2*v0;
                    v1 = 3.f*r1.y + gg1*r2.y + gg2*v1;
                }
                st2<OutT>(C + base + nl, v0, v1);
            }
        }
    }
}

// ===================== small FMA GEMM (CoordAtt yca only) =============
__global__ __launch_bounds__(256) void gemm_small_hsw(
    const float* __restrict__ A, const float* __restrict__ B,
    const float* __restrict__ bias, float* __restrict__ C,
    int M, int N, int K, int ldb, long sB, long sC)
{
    int b = blockIdx.z;
    B += (long)b*sB; C += (long)b*sC;
    int m0 = blockIdx.y*64, n0 = blockIdx.x*64;
    __shared__ float As[16][64], Bs[16][65];
    int tid = threadIdx.x, tx = tid & 15, ty = tid >> 4;
    float acc[4][4] = {};
    for (int k0 = 0; k0 < K; k0 += 16) {
        int i = tid >> 2, jb = (tid & 3)*4, mI = m0 + i;
        #pragma unroll
        for (int j = 0; j < 4; j++) {
            int k = k0 + jb + j;
            As[jb+j][i] = (mI < M && k < K) ? A[(long)mI*K + k] : 0.f;
        }
        int jr = tid >> 4, nb = (tid & 15)*4, k = k0 + jr;
        #pragma unroll
        for (int n = 0; n < 4; n++) {
            int nn = n0 + nb + n;
            Bs[jr][nb+n] = (k < K && nn < N) ? B[(long)k*ldb + nn] : 0.f;
        }
        __syncthreads();
        #pragma unroll
        for (int j = 0; j < 16; j++) {
            float a[4], bb[4];
            #pragma unroll
            for (int i2 = 0; i2 < 4; i2++) a[i2]  = As[j][ty*4+i2];
            #pragma unroll
            for (int i2 = 0; i2 < 4; i2++) bb[i2] = Bs[j][tx*4+i2];
            #pragma unroll
            for (int i2 = 0; i2 < 4; i2++)
                #pragma unroll
                for (int jj = 0; jj < 4; jj++) acc[i2][jj] += a[i2]*bb[jj];
        }
        __syncthreads();
    }
    #pragma unroll
    for (int i = 0; i < 4; i++) {
        int mI = m0 + ty*4 + i;
        if (mI >= M) continue;
        float bv = bias ? bias[mI] : 0.f;
        #pragma unroll
        for (int jj = 0; jj < 4; jj++) {
            int n = n0 + tx*4 + jj;
            if (n >= N) continue;
            float v = acc[i][jj] + bv;
            float tq = fminf(fmaxf(v+3.f,0.f),6.f); v = v*tq*(1.f/6.f);  // h-swish
            C[(long)mI*N + n] = v;
        }
    }
}

// ===================== CoordAtt glue ==================================
__global__ void ca_pool_k(const float* __restrict__ x, float* __restrict__ pool)
{
    int c = blockIdx.x, b = blockIdx.y, t = threadIdx.x;
    const float* p = x + ((long)b*CH + c)*NPIX;
    float sh = 0.f, sw = 0.f;
    for (int i = 0; i < 64; i++) sh += p[t*64 + i];
    for (int i = 0; i < 64; i++) sw += p[i*64 + t];
    float* o = pool + ((long)b*CH + c)*128;
    o[t] = sh*(1.f/64.f); o[64+t] = sw*(1.f/64.f);
}

__global__ void ca_proj_k(const float* __restrict__ wh, const float* __restrict__ bh,
                          const float* __restrict__ ww, const float* __restrict__ bw)
{
    int hw = blockIdx.y, b = blockIdx.z;
    int idx = blockIdx.x*256 + threadIdx.x;
    int c = idx >> 6, pos = idx & 63;
    const float* W  = hw ? ww : wh;
    const float* Bi = hw ? bw : bh;
    const float* y  = g_yca + (long)b*MIPC*128 + (hw ? 64 : 0) + pos;
    float s = Bi[c];
    #pragma unroll
    for (int i = 0; i < MIPC; i++) s += W[c*MIPC + i] * y[i*128];
    float o = 1.f / (1.f + __expf(-s));
    float* dst = hw ? g_aw : g_ah;
    dst[((long)b*CH + c)*64 + pos] = o;
}

__global__ void ca_apply_k(const float* __restrict__ x)
{
    long i = blockIdx.x*256L + threadIdx.x;
    if (i >= (long)BATCH*CN) return;
    int c = (int)(i & 255); long t = i >> 8;
    int pix = (int)(t & 4095); int b = (int)(t >> 12);
    long bc = (long)b*CH + c;
    int y = pix >> 6, xx = pix & 63;
    g_r[i] = __float2half(
        x[(long)b*CN + (long)c*NPIX + pix] * g_aw[bc*64+xx] * g_ah[bc*64+y]);
}

// ============ fused maxpool 5/9/13 (one plane per block) ===============
__global__ __launch_bounds__(256) void mp_all_k(__half* __restrict__ cat)
{
    __shared__ __half2 p0[4096], p1[4096];
    int c2 = blockIdx.x, b = blockIdx.y;
    __half2* base = (__half2*)(cat + (long)b*NPIX*1024);  // pix stride 512 half2
    int tid = threadIdx.x;
    #pragma unroll
    for (int i = tid; i < 4096; i += 256) p0[i] = base[(long)i*512 + c2];
    __syncthreads();
    #pragma unroll
    for (int pass = 1; pass <= 3; pass++) {
        #pragma unroll 4
        for (int i = tid; i < 4096; i += 256) {
            int x = i & 63;
            __half2 m = p0[i];
            if (x >= 1)  m = __hmax2(m, p0[i-1]);
            if (x >= 2)  m = __hmax2(m, p0[i-2]);
            if (x <= 62) m = __hmax2(m, p0[i+1]);
            if (x <= 61) m = __hmax2(m, p0[i+2]);
            p1[i] = m;
        }
        __syncthreads();
        #pragma unroll 4
        for (int i = tid; i < 4096; i += 256) {
            int y = i >> 6;
            __half2 m = p1[i];
            if (y >= 1)  m = __hmax2(m, p1[i-64]);
            if (y >= 2)  m = __hmax2(m, p1[i-128]);
            if (y <= 62) m = __hmax2(m, p1[i+64]);
            if (y <= 61) m = __hmax2(m, p1[i+128]);
            p0[i] = m;
            base[(long)i*512 + pass*128 + c2] = m;
        }
        __syncthreads();
    }
}

// ===================== PAM softmax (half rows of 4096) =================
__global__ void softmax_row_k(__half* __restrict__ a)
{
    __half2* p = (__half2*)(a + (long)blockIdx.x * 4096);
    int t = threadIdx.x;
    __shared__ float red[256];
    float2 v[8];
    #pragma unroll
    for (int i = 0; i < 8; i++) v[i] = __half22float2(p[t + i*256]);
    float mx = v[0].x;
    #pragma unroll
    for (int i = 0; i < 8; i++) { mx = fmaxf(mx, v[i].x); mx = fmaxf(mx, v[i].y); }
    red[t] = mx; __syncthreads();
    for (int s = 128; s > 0; s >>= 1) { if (t < s) red[t] = fmaxf(red[t], red[t+s]); __syncthreads(); }
    mx = red[0]; __syncthreads();
    float sum = 0.f;
    #pragma unroll
    for (int i = 0; i < 8; i++) {
        v[i].x = __expf(v[i].x - mx); v[i].y = __expf(v[i].y - mx);
        sum += v[i].x + v[i].y;
    }
    red[t] = sum; __syncthreads();
    for (int s = 128; s > 0; s >>= 1) { if (t < s) red[t] += red[t+s]; __syncthreads(); }
    float inv = 1.f / red[0];
    #pragma unroll
    for (int i = 0; i < 8; i++)
        p[t + i*256] = __floats2half2_rn(v[i].x * inv, v[i].y * inv);
}

// ===================== CAM: split-K reduce + softmax ===================
__global__ void e_reduce_k(const float* __restrict__ ep, float* __restrict__ e)
{
    int i = blockIdx.x*256 + threadIdx.x;
    int b = i >> 16, r = i & 65535;
    float s = 0.f;
    #pragma unroll
    for (int k = 0; k < ESPLIT; k++)
        s += ep[((long)(b*ESPLIT + k) << 16) + r];
    e[i] = s;
}

__global__ void cam_softmax_k(const float* __restrict__ e, __half* __restrict__ ac)
{
    long row = blockIdx.x;
    const float* p = e + row*256;
    int t = threadIdx.x;
    __shared__ float sm[256];
    float v = p[t];
    sm[t] = v; __syncthreads();
    for (int s = 128; s > 0; s >>= 1) { if (t < s) sm[t] = fmaxf(sm[t], sm[t+s]); __syncthreads(); }
    float rowmax = sm[0]; __syncthreads();
    float z = rowmax - v;
    sm[t] = z; __syncthreads();
    for (int s = 128; s > 0; s >>= 1) { if (t < s) sm[t] = fmaxf(sm[t], sm[t+s]); __syncthreads(); }
    float zm = sm[0]; __syncthreads();
    float pe = __expf(z - zm);
    sm[t] = pe; __syncthreads();
    for (int s = 128; s > 0; s >>= 1) { if (t < s) sm[t] += sm[t+s]; __syncthreads(); }
    ac[row*256 + t] = __float2half(pe / sm[0]);
}

// ============ tiled transpose NHWC(f32) -> NCHW f32 + half =============
__global__ void transpose_k(const float* __restrict__ src)
{
    __shared__ float s[32][33];
    int b = blockIdx.z;
    int p0 = blockIdx.x*32, c0 = blockIdx.y*32;
    int tx = threadIdx.x, ty = threadIdx.y;  // 32 x 8
    const float* S = src + (long)b*CN;
    float*  D32 = g_resT32 + (long)b*CN;
    __half* D16 = g_resT16 + (long)b*CN;
    #pragma unroll
    for (int j = 0; j < 32; j += 8)
        s[ty+j][tx] = S[(long)(p0+ty+j)*256 + c0+tx];
    __syncthreads();
    #pragma unroll
    for (int j = 0; j < 32; j += 8) {
        float v = s[tx][ty+j];
        long o = (long)(c0+ty+j)*4096 + p0+tx;
        D32[o] = v;
        D16[o] = __float2half(v);
    }
}

// ======================================================================
extern "C" void kernel_launch(void* const* d_in, const int* in_sizes, int n_in,
                              void* d_out, int out_size)
{
    const float* x     = (const float*)d_in[0];
    const float* ca_w1 = (const float*)d_in[1];
    const float* ca_b1 = (const float*)d_in[2];
    const float* ca_bn = (const float*)d_in[3];
    const float* ca_wh = (const float*)d_in[4];
    const float* ca_bh = (const float*)d_in[5];
    const float* ca_ww = (const float*)d_in[6];
    const float* ca_bw = (const float*)d_in[7];
    const float* s1_w  = (const float*)d_in[8];  const float* s1_bn = (const float*)d_in[9];
    const float* s2_w  = (const float*)d_in[10]; const float* s2_bn = (const float*)d_in[11];
    const float* s3_w  = (const float*)d_in[12]; const float* s3_bn = (const float*)d_in[13];
    const float* s4_w  = (const float*)d_in[14]; const float* s4_bn = (const float*)d_in[15];
    const float* s5_w  = (const float*)d_in[16]; const float* s5_bn = (const float*)d_in[17];
    const float* s6_w  = (const float*)d_in[18]; const float* s6_bn = (const float*)d_in[19];
    const float* s7_w  = (const float*)d_in[20]; const float* s7_bn = (const float*)d_in[21];
    const float* pq_w  = (const float*)d_in[22]; const float* pq_b  = (const float*)d_in[23];
    const float* pk_w  = (const float*)d_in[24]; const float* pk_b  = (const float*)d_in[25];
    const float* pv_w  = (const float*)d_in[26]; const float* pv_b  = (const float*)d_in[27];
    const float* gpa   = (const float*)d_in[28];
    const float* gca   = (const float*)d_in[29];

    float *pool,*yca,*res32,*pam,*e,*epart,*w1f,*b1f,*bs1,*bs2,*bs3,*bs4,*bs5,*bs6,*bs7,*bqk;
    __half *r16,*t1,*t2,*cat,*yc,*res16,*resT16,*qk,*vb,*attn,*ac;
    __half *ws1,*ws2,*ws3,*ws4,*ws5,*ws6,*ws7,*wqk,*wpv;
    float *resT32;
    cudaGetSymbolAddress((void**)&pool, g_pool);    cudaGetSymbolAddress((void**)&yca, g_yca);
    cudaGetSymbolAddress((void**)&r16, g_r);        cudaGetSymbolAddress((void**)&t1, g_t1);
    cudaGetSymbolAddress((void**)&t2, g_t2);        cudaGetSymbolAddress((void**)&cat, g_cat);
    cudaGetSymbolAddress((void**)&yc, g_yc);
    cudaGetSymbolAddress((void**)&res16, g_res16);  cudaGetSymbolAddress((void**)&res32, g_res32);
    cudaGetSymbolAddress((void**)&resT16, g_resT16);cudaGetSymbolAddress((void**)&resT32, g_resT32);
    cudaGetSymbolAddress((void**)&qk, g_qk);        cudaGetSymbolAddress((void**)&vb, g_v);
    cudaGetSymbolAddress((void**)&attn, g_attn);    cudaGetSymbolAddress((void**)&pam, g_pam);
    cudaGetSymbolAddress((void**)&e, g_e);          cudaGetSymbolAddress((void**)&epart, g_epart);
    cudaGetSymbolAddress((void**)&ac, g_ac);
    cudaGetSymbolAddress((void**)&w1f, g_w1f);      cudaGetSymbolAddress((void**)&b1f, g_b1f);
    cudaGetSymbolAddress((void**)&ws1, g_ws1);      cudaGetSymbolAddress((void**)&bs1, g_bs1);
    cudaGetSymbolAddress((void**)&ws2, g_ws2);      cudaGetSymbolAddress((void**)&bs2, g_bs2);
    cudaGetSymbolAddress((void**)&ws3, g_ws3);      cudaGetSymbolAddress((void**)&bs3, g_bs3);
    cudaGetSymbolAddress((void**)&ws4, g_ws4);      cudaGetSymbolAddress((void**)&bs4, g_bs4);
    cudaGetSymbolAddress((void**)&ws5, g_ws5);      cudaGetSymbolAddress((void**)&bs5, g_bs5);
    cudaGetSymbolAddress((void**)&ws6, g_ws6);      cudaGetSymbolAddress((void**)&bs6, g_bs6);
    cudaGetSymbolAddress((void**)&ws7, g_ws7);      cudaGetSymbolAddress((void**)&bs7, g_bs7);
    cudaGetSymbolAddress((void**)&wqk, g_wqk);      cudaGetSymbolAddress((void**)&bqk, g_bqk);
    cudaGetSymbolAddress((void**)&wpv, g_wpv);

    const int SMEMSZ = SMEM_WORDS * 4;   // 61440 B
    cudaFuncSetAttribute(mma_gemm<0,false,__half>, cudaFuncAttributeMaxDynamicSharedMemorySize, SMEMSZ);
    cudaFuncSetAttribute(mma_gemm<0,false,float>,  cudaFuncAttributeMaxDynamicSharedMemorySize, SMEMSZ);
    cudaFuncSetAttribute(mma_gemm<1,false,__half>, cudaFuncAttributeMaxDynamicSharedMemorySize, SMEMSZ);
    cudaFuncSetAttribute(mma_gemm<1,true,__half>,  cudaFuncAttributeMaxDynamicSharedMemorySize, SMEMSZ);
    cudaFuncSetAttribute(mma_gemm<4,false,float>,  cudaFuncAttributeMaxDynamicSharedMemorySize, SMEMSZ);

    const int EB  = (BATCH*CN + 255)/256;

    // ---- merged fold/convert ----
    FoldArgs fa;
    fa.w[0]=ca_w1; fa.bn[0]=ca_bn; fa.bin[0]=ca_b1; fa.wf[0]=nullptr; fa.bf[0]=b1f; fa.O[0]=MIPC; fa.Ke[0]=256;  fa.ro[0]=0;
    fa.w[1]=s1_w;  fa.bn[1]=s1_bn; fa.bin[1]=nullptr; fa.wf[1]=ws1; fa.bf[1]=bs1; fa.O[1]=CH; fa.Ke[1]=256;  fa.ro[1]=0;
    fa.w[2]=s2_w;  fa.bn[2]=s2_bn; fa.bin[2]=nullptr; fa.wf[2]=ws2; fa.bf[2]=bs2; fa.O[2]=CH; fa.Ke[2]=256;  fa.ro[2]=0;
    fa.w[3]=s3_w;  fa.bn[3]=s3_bn; fa.bin[3]=nullptr; fa.wf[3]=ws3; fa.bf[3]=bs3; fa.O[3]=CH; fa.Ke[3]=2304; fa.ro[3]=1;
    fa.w[4]=s4_w;  fa.bn[4]=s4_bn; fa.bin[4]=nullptr; fa.wf[4]=ws4; fa.bf[4]=bs4; fa.O[4]=CH; fa.Ke[4]=256;  fa.ro[4]=0;
    fa.w[5]=s5_w;  fa.bn[5]=s5_bn; fa.bin[5]=nullptr; fa.wf[5]=ws5; fa.bf[5]=bs5; fa.O[5]=CH; fa.Ke[5]=1024; fa.ro[5]=0;
    fa.w[6]=s6_w;  fa.bn[6]=s6_bn; fa.bin[6]=nullptr; fa.wf[6]=ws6; fa.bf[6]=bs6; fa.O[6]=CH; fa.Ke[6]=2304; fa.ro[6]=1;
    fa.w[7]=s7_w;  fa.bn[7]=s7_bn; fa.bin[7]=nullptr; fa.wf[7]=ws7; fa.bf[7]=bs7; fa.O[7]=CH; fa.Ke[7]=512;  fa.ro[7]=0;
    fa.w1f_f=w1f;
    fa.pq_w=pq_w; fa.pq_b=pq_b; fa.pk_w=pk_w; fa.pk_b=pk_b; fa.pv_w=pv_w;
    fa.qkw=wqk; fa.qkb=bqk; fa.pvw=wpv;
    fold_all_k<<<dim3(256,10),256>>>(fa);

    // ---- CoordAtt ----
    ca_pool_k<<<dim3(CH,BATCH),64>>>(x, pool);
    gemm_small_hsw<<<dim3(2,1,BATCH),256>>>(w1f, pool, b1f, yca,
        MIPC,128,CH, 128, (long)CH*128, (long)MIPC*128);
    ca_proj_k<<<dim3(64,2,BATCH),256>>>(ca_wh, ca_bh, ca_ww, ca_bw);
    ca_apply_k<<<EB,256>>>(x);

    // ---- SPPCSPC ----
    mma_gemm<1,false,__half><<<dim3(2,32,BATCH),128,SMEMSZ>>>(r16, ws1, bs1, t1,
        256,256,256,256, 256,256,0, (long)CN,0,(long)CN);
    mma_gemm<1,true,__half><<<dim3(2,32,BATCH),128,SMEMSZ>>>(t1, ws3, bs3, t2,
        2304,256,2304,256, 256,256,0, (long)CN,0,(long)CN);
    mma_gemm<1,false,__half><<<dim3(2,32,BATCH),128,SMEMSZ>>>(t2, ws4, bs4, cat,
        256,256,256,1024, 256,256,0, (long)CN,0,(long)NPIX*1024);
    mp_all_k<<<dim3(128,BATCH),256>>>(cat);
    mma_gemm<1,false,__half><<<dim3(2,32,BATCH),128,SMEMSZ>>>(cat, ws5, bs5, t1,
        1024,1024,1024,256, 256,256,0, (long)NPIX*1024,0,(long)CN);
    mma_gemm<1,true,__half><<<dim3(2,32,BATCH),128,SMEMSZ>>>(t1, ws6, bs6, yc,
        2304,256,2304,512, 256,256,0, (long)CN,0,(long)NPIX*512);
    mma_gemm<1,false,__half><<<dim3(2,32,BATCH),128,SMEMSZ>>>(r16, ws2, bs2, yc+256,
        256,256,256,512, 256,256,0, (long)CN,0,(long)NPIX*512);
    // s7: half out + f32 aux (residual path)
    mma_gemm<1,false,__half><<<dim3(2,32,BATCH),128,SMEMSZ>>>(yc, ws7, bs7, res16,
        512,512,512,256, 256,256,0, (long)NPIX*512,0,(long)CN, 1, res32);

    // ---- PAM ----
    mma_gemm<0,false,__half><<<dim3(1,32,BATCH),128,SMEMSZ>>>(res16, wqk, bqk, qk,
        256,256,256,64, 64,64,0, (long)CN,0,(long)NPIX*64);
    mma_gemm<0,false,__half><<<dim3(32,2,BATCH),128,SMEMSZ>>>(wpv, res16, pv_b, vb,
        256,256,256,NPIX, NPIX,NPIX,1, 0,(long)CN,(long)CN);
    mma_gemm<0,false,__half><<<dim3(32,32,BATCH),128,SMEMSZ>>>(qk, qk+32, nullptr, attn,
        CQD,64,64,NPIX, NPIX,NPIX,0, (long)NPIX*64,(long)NPIX*64,(long)NPIX*NPIX);
    softmax_row_k<<<BATCH*NPIX,256>>>(attn);
    mma_gemm<0,false,float><<<dim3(32,2,BATCH),128,SMEMSZ>>>(vb, attn, nullptr, pam,
        NPIX,NPIX,NPIX,NPIX, NPIX,NPIX,0, (long)CN,(long)NPIX*NPIX,(long)CN);

    // ---- CAM ----
    transpose_k<<<dim3(128,8,BATCH),dim3(32,8)>>>(res32);
    mma_gemm<0,false,float><<<dim3(2,2,BATCH*ESPLIT),128,SMEMSZ>>>(resT16, resT16, nullptr, epart,
        NPIX/ESPLIT,NPIX,NPIX,256, 256,256,0, (long)CN,(long)CN,(long)CH*CH, ESPLIT);
    e_reduce_k<<<(BATCH*CH*CH+255)/256,256>>>(epart, e);
    cam_softmax_k<<<BATCH*CH,256>>>(e, ac);
    mma_gemm<4,false,float><<<dim3(32,2,BATCH),128,SMEMSZ>>>(ac, res16, nullptr, (float*)d_out,
        256,256,256,NPIX, NPIX,NPIX,0, (long)CH*CH,(long)CN,(long)CN,
        1, nullptr, resT32, pam, gpa, gca);
}